// round 2
// baseline (speedup 1.0000x reference)
#include <cuda_runtime.h>
#include <math.h>

#define NB 4
#define NL 2048
#define ND 1024
#define NH 16
#define NHD 64
#define NT (NB*NL)

// ---------------- scratch (device globals: no allocations allowed) ----------
__device__ float g_q[(size_t)NB*NH*NL*NHD];     // [bh][l][hd]
__device__ float g_k[(size_t)NB*NH*NL*NHD];
__device__ float g_v[(size_t)NB*NH*NL*NHD];
__device__ float g_attn[(size_t)NT*ND];         // [t][h*64+hd]
__device__ float g_cos[NL*(NHD/2)];
__device__ float g_sin[NL*(NHD/2)];

// ---------------- K0: RoPE tables (fp64 for accuracy) ------------------------
__global__ void rope_tables_kernel() {
    int idx = blockIdx.x * 256 + threadIdx.x;
    if (idx >= NL * (NHD/2)) return;
    int l = idx >> 5;
    int i = idx & 31;
    double inv = exp(-((double)(2*i) / (double)NHD) * log(10000.0));
    double a = (double)l * inv;
    g_cos[idx] = (float)cos(a);
    g_sin[idx] = (float)sin(a);
}

// ---------------- K1: fused QKV projection + RoPE ----------------------------
// Y[t,o] = sum_d X[t,d]*W[o,d] + b[o];  blockIdx.z selects Q/K/V.
// 64x64 tile, BK=16, 256 threads, 4x4 microtile.
__global__ void __launch_bounds__(256) qkv_proj_kernel(
    const float* __restrict__ X,
    const float* __restrict__ Wq, const float* __restrict__ bq,
    const float* __restrict__ Wk, const float* __restrict__ bk,
    const float* __restrict__ Wv, const float* __restrict__ bv)
{
    __shared__ float Xs[16*68];   // [k][m]
    __shared__ float Ws[16*68];   // [k][n]
    const int tx = threadIdx.x & 15;
    const int ty = threadIdx.x >> 4;
    const int tid = threadIdx.x;
    const int lr = tid >> 2;      // 0..63
    const int lq = tid & 3;       // 0..3

    const int z = blockIdx.z;
    const float* W    = (z == 0) ? Wq : (z == 1) ? Wk : Wv;
    const float* bias = (z == 0) ? bq : (z == 1) ? bk : bv;
    float* dst        = (z == 0) ? g_q : (z == 1) ? g_k : g_v;

    const int rowg = blockIdx.y * 64 + lr;   // t for X load
    const int colg = blockIdx.x * 64 + lr;   // o for W load

    float acc[4][4] = {};
    for (int k0 = 0; k0 < ND; k0 += 16) {
        float4 xv = *(const float4*)(X + (size_t)rowg * ND + k0 + lq*4);
        float4 wv = *(const float4*)(W + (size_t)colg * ND + k0 + lq*4);
        __syncthreads();
        Xs[(lq*4+0)*68 + lr] = xv.x;
        Xs[(lq*4+1)*68 + lr] = xv.y;
        Xs[(lq*4+2)*68 + lr] = xv.z;
        Xs[(lq*4+3)*68 + lr] = xv.w;
        Ws[(lq*4+0)*68 + lr] = wv.x;
        Ws[(lq*4+1)*68 + lr] = wv.y;
        Ws[(lq*4+2)*68 + lr] = wv.z;
        Ws[(lq*4+3)*68 + lr] = wv.w;
        __syncthreads();
        #pragma unroll
        for (int k = 0; k < 16; k++) {
            float4 a4 = *(const float4*)&Xs[k*68 + 4*ty];
            float4 b4 = *(const float4*)&Ws[k*68 + 4*tx];
            float a[4] = {a4.x, a4.y, a4.z, a4.w};
            float b[4] = {b4.x, b4.y, b4.z, b4.w};
            #pragma unroll
            for (int i = 0; i < 4; i++)
                #pragma unroll
                for (int j = 0; j < 4; j++)
                    acc[i][j] += a[i] * b[j];
        }
    }

    // epilogue: bias (+RoPE for q,k), relayout to [bh][l][hd]
    const int c0 = blockIdx.x * 64 + 4*tx;
    const int h  = c0 >> 6;
    const int hd = c0 & 63;
    #pragma unroll
    for (int i = 0; i < 4; i++) {
        int t = blockIdx.y * 64 + 4*ty + i;
        int b = t >> 11;
        int l = t & (NL - 1);
        float y[4];
        #pragma unroll
        for (int j = 0; j < 4; j++) y[j] = acc[i][j] + bias[c0 + j];
        if (z < 2) {
            int p0 = hd >> 1;          // even, pairs (p0, p0+1)
            float c1 = g_cos[l*32 + p0],     s1 = g_sin[l*32 + p0];
            float c2 = g_cos[l*32 + p0 + 1], s2 = g_sin[l*32 + p0 + 1];
            float e = y[0], o = y[1];
            y[0] = e*c1 - o*s1;  y[1] = e*s1 + o*c1;
            e = y[2]; o = y[3];
            y[2] = e*c2 - o*s2;  y[3] = e*s2 + o*c2;
        }
        size_t off = (((size_t)(b*NH + h))*NL + l)*NHD + hd;
        *(float4*)&dst[off] = make_float4(y[0], y[1], y[2], y[3]);
    }
}

// ---------------- tile loaders for attention ---------------------------------
// load [64 x 64] f32 tile (row stride 64) transposed into smem [d][row], stride 68
__device__ __forceinline__ void load_tile_T(const float* __restrict__ g, float* s, int tid) {
    int row  = tid >> 2;
    int quad = tid & 3;
    const float4* gp = (const float4*)(g + row * 64);
    #pragma unroll
    for (int seg = 0; seg < 4; seg++) {
        float4 x = gp[quad + seg*4];
        int d0 = (quad + seg*4) * 4;
        s[(d0+0)*68 + row] = x.x;
        s[(d0+1)*68 + row] = x.y;
        s[(d0+2)*68 + row] = x.z;
        s[(d0+3)*68 + row] = x.w;
    }
}
// natural copy [row][col], stride 68
__device__ __forceinline__ void load_tile(const float* __restrict__ g, float* s, int tid) {
    int row  = tid >> 2;
    int quad = tid & 3;
    const float4* gp = (const float4*)(g + row * 64);
    float4* sp = (float4*)(s + row * 68);
    #pragma unroll
    for (int seg = 0; seg < 4; seg++)
        sp[quad + seg*4] = gp[quad + seg*4];
}

// ---------------- K2: causal flash attention ---------------------------------
// grid (L/64, B*H), 256 threads. Each CTA: 64 query rows of one (b,h).
__global__ void __launch_bounds__(256) attn_kernel() {
    extern __shared__ float sm[];
    float* Qs = sm;             // [d][row]  64x68
    float* Ks = sm + 64*68;     // [d][col]
    float* Vs = sm + 2*64*68;   // [c][vc]
    float* Ps = sm + 3*64*68;   // [c][row]

    const int tid = threadIdx.x;
    const int tx = tid & 15;
    const int ty = tid >> 4;
    const int bh = blockIdx.y;
    const int q0 = blockIdx.x * 64;

    const float* qbase = g_q + (size_t)bh * (NL*NHD);
    const float* kbase = g_k + (size_t)bh * (NL*NHD);
    const float* vbase = g_v + (size_t)bh * (NL*NHD);

    load_tile_T(qbase + (size_t)q0 * 64, Qs, tid);

    float m[4], lsum[4], O[4][4];
    #pragma unroll
    for (int i = 0; i < 4; i++) {
        m[i] = -1e30f; lsum[i] = 0.f;
        #pragma unroll
        for (int j = 0; j < 4; j++) O[i][j] = 0.f;
    }

    for (int j0 = 0; j0 <= q0; j0 += 64) {
        __syncthreads();   // protect Ks/Vs/Ps reuse (also covers initial Qs fill)
        load_tile_T(kbase + (size_t)j0 * 64, Ks, tid);
        load_tile  (vbase + (size_t)j0 * 64, Vs, tid);
        __syncthreads();

        // S = (Q K^T) * scale
        float s[4][4] = {};
        #pragma unroll 16
        for (int d = 0; d < 64; d++) {
            float4 a4 = *(const float4*)&Qs[d*68 + 4*ty];
            float4 b4 = *(const float4*)&Ks[d*68 + 4*tx];
            float a[4] = {a4.x, a4.y, a4.z, a4.w};
            float b[4] = {b4.x, b4.y, b4.z, b4.w};
            #pragma unroll
            for (int i = 0; i < 4; i++)
                #pragma unroll
                for (int j = 0; j < 4; j++)
                    s[i][j] += a[i] * b[j];
        }
        const float scale = 0.125f;   // 1/sqrt(64)
        if (j0 == q0) {
            #pragma unroll
            for (int i = 0; i < 4; i++)
                #pragma unroll
                for (int j = 0; j < 4; j++) {
                    s[i][j] *= scale;
                    if (j0 + 4*tx + j > q0 + 4*ty + i) s[i][j] = -1e30f;
                }
        } else {
            #pragma unroll
            for (int i = 0; i < 4; i++)
                #pragma unroll
                for (int j = 0; j < 4; j++) s[i][j] *= scale;
        }

        // online softmax (row reduction across the 16 tx lanes of the half-warp)
        float tm[4];
        #pragma unroll
        for (int i = 0; i < 4; i++)
            tm[i] = fmaxf(fmaxf(s[i][0], s[i][1]), fmaxf(s[i][2], s[i][3]));
        #pragma unroll
        for (int off = 1; off < 16; off <<= 1)
            #pragma unroll
            for (int i = 0; i < 4; i++)
                tm[i] = fmaxf(tm[i], __shfl_xor_sync(0xffffffffu, tm[i], off));

        float alpha[4], rs[4];
        #pragma unroll
        for (int i = 0; i < 4; i++) {
            float mn = fmaxf(m[i], tm[i]);
            alpha[i] = __expf(m[i] - mn);
            m[i] = mn;
            #pragma unroll
            for (int j = 0; j < 4; j++) s[i][j] = __expf(s[i][j] - mn);
            rs[i] = (s[i][0] + s[i][1]) + (s[i][2] + s[i][3]);
        }
        #pragma unroll
        for (int off = 1; off < 16; off <<= 1)
            #pragma unroll
            for (int i = 0; i < 4; i++)
                rs[i] += __shfl_xor_sync(0xffffffffu, rs[i], off);
        #pragma unroll
        for (int i = 0; i < 4; i++) {
            lsum[i] = lsum[i] * alpha[i] + rs[i];
            #pragma unroll
            for (int j = 0; j < 4; j++) O[i][j] *= alpha[i];
        }

        // P to smem as [col][row]
        #pragma unroll
        for (int i = 0; i < 4; i++)
            #pragma unroll
            for (int j = 0; j < 4; j++)
                Ps[(4*tx + j)*68 + 4*ty + i] = s[i][j];
        __syncthreads();

        // O += P V
        #pragma unroll 16
        for (int c = 0; c < 64; c++) {
            float4 p4 = *(const float4*)&Ps[c*68 + 4*ty];
            float4 v4 = *(const float4*)&Vs[c*68 + 4*tx];
            float p[4] = {p4.x, p4.y, p4.z, p4.w};
            float v[4] = {v4.x, v4.y, v4.z, v4.w};
            #pragma unroll
            for (int i = 0; i < 4; i++)
                #pragma unroll
                for (int j = 0; j < 4; j++)
                    O[i][j] += p[i] * v[j];
        }
    }

    // write to g_attn [t][h*64+hd]
    const int b = bh >> 4;
    const int h = bh & 15;
    #pragma unroll
    for (int i = 0; i < 4; i++) {
        float rinv = 1.0f / lsum[i];
        int t = b * NL + q0 + 4*ty + i;
        size_t off = (size_t)t * ND + h*64 + 4*tx;
        *(float4*)&g_attn[off] = make_float4(O[i][0]*rinv, O[i][1]*rinv,
                                             O[i][2]*rinv, O[i][3]*rinv);
    }
}

// ---------------- K3: output projection --------------------------------------
__global__ void __launch_bounds__(256) out_proj_kernel(
    const float* __restrict__ W, const float* __restrict__ bias,
    float* __restrict__ out)
{
    __shared__ float Xs[16*68];
    __shared__ float Ws[16*68];
    const int tx = threadIdx.x & 15;
    const int ty = threadIdx.x >> 4;
    const int tid = threadIdx.x;
    const int lr = tid >> 2;
    const int lq = tid & 3;

    const int rowg = blockIdx.y * 64 + lr;
    const int colg = blockIdx.x * 64 + lr;

    float acc[4][4] = {};
    for (int k0 = 0; k0 < ND; k0 += 16) {
        float4 xv = *(const float4*)(g_attn + (size_t)rowg * ND + k0 + lq*4);
        float4 wv = *(const float4*)(W + (size_t)colg * ND + k0 + lq*4);
        __syncthreads();
        Xs[(lq*4+0)*68 + lr] = xv.x;
        Xs[(lq*4+1)*68 + lr] = xv.y;
        Xs[(lq*4+2)*68 + lr] = xv.z;
        Xs[(lq*4+3)*68 + lr] = xv.w;
        Ws[(lq*4+0)*68 + lr] = wv.x;
        Ws[(lq*4+1)*68 + lr] = wv.y;
        Ws[(lq*4+2)*68 + lr] = wv.z;
        Ws[(lq*4+3)*68 + lr] = wv.w;
        __syncthreads();
        #pragma unroll
        for (int k = 0; k < 16; k++) {
            float4 a4 = *(const float4*)&Xs[k*68 + 4*ty];
            float4 b4 = *(const float4*)&Ws[k*68 + 4*tx];
            float a[4] = {a4.x, a4.y, a4.z, a4.w};
            float b[4] = {b4.x, b4.y, b4.z, b4.w};
            #pragma unroll
            for (int i = 0; i < 4; i++)
                #pragma unroll
                for (int j = 0; j < 4; j++)
                    acc[i][j] += a[i] * b[j];
        }
    }
    const int c0 = blockIdx.x * 64 + 4*tx;
    #pragma unroll
    for (int i = 0; i < 4; i++) {
        int t = blockIdx.y * 64 + 4*ty + i;
        float y[4];
        #pragma unroll
        for (int j = 0; j < 4; j++) y[j] = acc[i][j] + bias[c0 + j];
        *(float4*)&out[(size_t)t * ND + c0] = make_float4(y[0], y[1], y[2], y[3]);
    }
}

// ---------------- launch -----------------------------------------------------
extern "C" void kernel_launch(void* const* d_in, const int* in_sizes, int n_in,
                              void* d_out, int out_size) {
    const float* X  = (const float*)d_in[0];
    const float* Wq = (const float*)d_in[1];
    const float* bq = (const float*)d_in[2];
    const float* Wk = (const float*)d_in[3];
    const float* bk = (const float*)d_in[4];
    const float* Wv = (const float*)d_in[5];
    const float* bv = (const float*)d_in[6];
    const float* Wo = (const float*)d_in[7];
    const float* bo = (const float*)d_in[8];
    float* out = (float*)d_out;

    rope_tables_kernel<<<(NL*(NHD/2) + 255)/256, 256>>>();

    dim3 gq(ND/64, NT/64, 3);
    qkv_proj_kernel<<<gq, 256>>>(X, Wq, bq, Wk, bk, Wv, bv);

    const int attn_smem = 4 * 64 * 68 * (int)sizeof(float);   // 69632 B
    cudaFuncSetAttribute(attn_kernel, cudaFuncAttributeMaxDynamicSharedMemorySize, attn_smem);
    attn_kernel<<<dim3(NL/64, NB*NH), 256, attn_smem>>>();

    out_proj_kernel<<<dim3(ND/64, NT/64), 256>>>(Wo, bo, out);
}

// round 5
// speedup vs baseline: 1.5679x; 1.5679x over previous
#include <cuda_runtime.h>
#include <cuda_bf16.h>
#include <stdint.h>
#include <math.h>

#define NB 4
#define NL 2048
#define ND 1024
#define NH 16
#define NHD 64
#define NT (NB*NL)

// ---------------- scratch (device globals: no allocations allowed) ----------
__device__ float g_q[(size_t)NB*NH*NL*NHD];     // [bh][l][hd]
__device__ float g_k[(size_t)NB*NH*NL*NHD];
__device__ float g_v[(size_t)NB*NH*NL*NHD];
__device__ float g_attn[(size_t)NT*ND];         // [t][h*64+hd]
__device__ float g_cos[NL*(NHD/2)];
__device__ float g_sin[NL*(NHD/2)];

// ---------------- helpers ----------------------------------------------------
__device__ __forceinline__ uint32_t smem_to_u32(const void* smem_ptr) {
    uint32_t addr;
    asm("{ .reg .u64 tmp; cvta.to.shared.u64 tmp, %1; cvt.u32.u64 %0, tmp; }"
        : "=r"(addr) : "l"(smem_ptr));
    return addr;
}
#define SWZ(off) ((off) ^ (((off) >> 3) & 0x70))

__device__ __forceinline__ void ldsm4(uint32_t* r, uint32_t a) {
    asm volatile("ldmatrix.sync.aligned.m8n8.x4.shared.b16 {%0,%1,%2,%3}, [%4];"
        : "=r"(r[0]), "=r"(r[1]), "=r"(r[2]), "=r"(r[3]) : "r"(a));
}
__device__ __forceinline__ void mma16816(float* c, const uint32_t* a,
                                         uint32_t b0, uint32_t b1) {
    asm volatile(
        "mma.sync.aligned.m16n8k16.row.col.f32.bf16.bf16.f32 "
        "{%0,%1,%2,%3}, {%4,%5,%6,%7}, {%8,%9}, {%0,%1,%2,%3};"
        : "+f"(c[0]), "+f"(c[1]), "+f"(c[2]), "+f"(c[3])
        : "r"(a[0]), "r"(a[1]), "r"(a[2]), "r"(a[3]), "r"(b0), "r"(b1));
}

// SMEM layout (bytes, relative to 1024-aligned base)
#define SOFF_AH 0
#define SOFF_AL 16384
#define SOFF_BH 32768
#define SOFF_BL 49152
#define GEMM_SMEM_BYTES (65536 + 1024)

// ---------------- K0: RoPE tables (fp64 for accuracy) ------------------------
__global__ void rope_tables_kernel() {
    int idx = blockIdx.x * 256 + threadIdx.x;
    if (idx >= NL * (NHD/2)) return;
    int l = idx >> 5;
    int i = idx & 31;
    double inv = exp(-((double)(2*i) / (double)NHD) * log(10000.0));
    double a = (double)l * inv;
    g_cos[idx] = (float)cos(a);
    g_sin[idx] = (float)sin(a);
}

// ---------------- bf16 hi/lo split store into swizzled smem ------------------
__device__ __forceinline__ void cvt_store(char* sh, char* sl, int r, int f4, float4 x) {
    __nv_bfloat162 h01, h23, l01, l23;
    h01.x = __float2bfloat16(x.x); h01.y = __float2bfloat16(x.y);
    h23.x = __float2bfloat16(x.z); h23.y = __float2bfloat16(x.w);
    l01.x = __float2bfloat16(x.x - __bfloat162float(h01.x));
    l01.y = __float2bfloat16(x.y - __bfloat162float(h01.y));
    l23.x = __float2bfloat16(x.z - __bfloat162float(h23.x));
    l23.y = __float2bfloat16(x.w - __bfloat162float(h23.y));
    uint32_t off = (uint32_t)(r * 128 + f4 * 8);
    uint32_t sw = SWZ(off);
    *(uint2*)(sh + sw) = make_uint2(*(uint32_t*)&h01, *(uint32_t*)&h23);
    *(uint2*)(sl + sw) = make_uint2(*(uint32_t*)&l01, *(uint32_t*)&l23);
}

// ---------------- shared GEMM mainloop: acc = A[m,:] * B[n,:]^T --------------
// A: [*, ND] fp32 row-major (rows mBase..mBase+127)
// B: [*, ND] fp32 row-major (rows nBase..nBase+127)   C = A * B^T
// 8 warps: wm = wid>>1 (4), wn = wid&1 (2). Warp tile 32x64.
// acc[i][j][4]: i = m16 tile (2), j = n8 tile (8).
__device__ __forceinline__ void gemm_mainloop_mma(
    const float* __restrict__ Amat, const float* __restrict__ Bmat,
    int mBase, int nBase, char* sbase, uint32_t sb, float acc[2][8][4])
{
    const int tid = threadIdx.x;
    const int lid = tid & 31;
    const int wid = tid >> 5;
    const int wm = wid >> 1;
    const int wn = wid & 1;
    const int f4 = tid & 15;
    const int r0 = tid >> 4;

    char* sAh = sbase + SOFF_AH;
    char* sAl = sbase + SOFF_AL;
    char* sBh = sbase + SOFF_BH;
    char* sBl = sbase + SOFF_BL;

    // ldmatrix lane address components (constant across stages except k0)
    const int a_row = wm*32 + (lid & 7) + ((lid >> 3) & 1) * 8;
    const int a_cb  = (lid >> 4) * 8;
    const int b_row = wn*64 + (lid & 7) + ((lid >> 4) & 1) * 8;
    const int b_cb  = ((lid >> 3) & 1) * 8;

    for (int stage = 0; stage < ND/64; stage++) {
        const int k0g = stage * 64;
        // issue global loads first (latency overlaps barrier wait)
        float4 xa[8], xb[8];
        #pragma unroll
        for (int rr = 0; rr < 8; rr++) {
            int r = rr * 16 + r0;
            xa[rr] = *(const float4*)(Amat + (size_t)(mBase + r) * ND + k0g + f4*4);
            xb[rr] = *(const float4*)(Bmat + (size_t)(nBase + r) * ND + k0g + f4*4);
        }
        __syncthreads();   // previous stage's ldmatrix done
        #pragma unroll
        for (int rr = 0; rr < 8; rr++) {
            int r = rr * 16 + r0;
            cvt_store(sAh, sAl, r, f4, xa[rr]);
            cvt_store(sBh, sBl, r, f4, xb[rr]);
        }
        __syncthreads();

        #pragma unroll
        for (int ks = 0; ks < 4; ks++) {
            const int k0 = ks * 16;
            uint32_t ah[2][4], al[2][4], bh[4][4], bl[4][4];
            #pragma unroll
            for (int i = 0; i < 2; i++) {
                uint32_t off = (uint32_t)((a_row + i*16) * 128 + (k0 + a_cb) * 2);
                uint32_t sw = SWZ(off);
                ldsm4(ah[i], sb + SOFF_AH + sw);
                ldsm4(al[i], sb + SOFF_AL + sw);
            }
            #pragma unroll
            for (int jj = 0; jj < 4; jj++) {
                uint32_t off = (uint32_t)((b_row + jj*16) * 128 + (k0 + b_cb) * 2);
                uint32_t sw = SWZ(off);
                ldsm4(bh[jj], sb + SOFF_BH + sw);
                ldsm4(bl[jj], sb + SOFF_BL + sw);
            }
            #pragma unroll
            for (int i = 0; i < 2; i++)
                #pragma unroll
                for (int jj = 0; jj < 4; jj++) {
                    mma16816(acc[i][2*jj],   ah[i], bh[jj][0], bh[jj][1]);
                    mma16816(acc[i][2*jj+1], ah[i], bh[jj][2], bh[jj][3]);
                    mma16816(acc[i][2*jj],   ah[i], bl[jj][0], bl[jj][1]);
                    mma16816(acc[i][2*jj+1], ah[i], bl[jj][2], bl[jj][3]);
                    mma16816(acc[i][2*jj],   al[i], bh[jj][0], bh[jj][1]);
                    mma16816(acc[i][2*jj+1], al[i], bh[jj][2], bh[jj][3]);
                }
        }
    }
}

// ---------------- K1: fused QKV projection + RoPE (mma.sync) -----------------
__global__ void __launch_bounds__(256, 1)
qkv_mma_kernel(const float* __restrict__ X,
               const float* __restrict__ Wq, const float* __restrict__ bq,
               const float* __restrict__ Wk, const float* __restrict__ bk,
               const float* __restrict__ Wv, const float* __restrict__ bv)
{
    extern __shared__ char dsm[];
    char* sbase = (char*)((((uintptr_t)dsm) + 1023) & ~(uintptr_t)1023);
    uint32_t sb = smem_to_u32(sbase);
    const int tid = threadIdx.x;
    const int lid = tid & 31;
    const int wid = tid >> 5;
    const int wm = wid >> 1;
    const int wn = wid & 1;

    const int z = blockIdx.z;
    const float* W    = (z == 0) ? Wq : (z == 1) ? Wk : Wv;
    const float* bias = (z == 0) ? bq : (z == 1) ? bk : bv;
    float* dst        = (z == 0) ? g_q : (z == 1) ? g_k : g_v;

    const int mBase = blockIdx.y * 128;
    const int nBase = blockIdx.x * 128;

    float acc[2][8][4] = {};
    gemm_mainloop_mma(X, W, mBase, nBase, sbase, sb, acc);

    // epilogue: bias + RoPE (q,k), relayout to [bh][l][hd]
    const int g  = lid >> 2;
    const int t4 = lid & 3;
    #pragma unroll
    for (int i = 0; i < 2; i++) {
        #pragma unroll
        for (int rr = 0; rr < 2; rr++) {
            int t = mBase + wm*32 + i*16 + g + rr*8;
            int b = t >> 11;
            int l = t & (NL - 1);
            #pragma unroll
            for (int j = 0; j < 8; j++) {
                int c = nBase + wn*64 + j*8 + 2*t4;
                float y0 = acc[i][j][rr*2+0] + bias[c];
                float y1 = acc[i][j][rr*2+1] + bias[c+1];
                if (z < 2) {
                    int p0 = (c & 63) >> 1;
                    float co = g_cos[l*32 + p0], si = g_sin[l*32 + p0];
                    float e = y0, o = y1;
                    y0 = e*co - o*si;
                    y1 = e*si + o*co;
                }
                int h  = c >> 6;
                int hd = c & 63;
                size_t off = (((size_t)(b*NH + h))*NL + l)*NHD + hd;
                *(float2*)&dst[off] = make_float2(y0, y1);
            }
        }
    }
}

// ---------------- K3: output projection (mma.sync) ---------------------------
__global__ void __launch_bounds__(256, 1)
out_mma_kernel(const float* __restrict__ W, const float* __restrict__ bias,
               float* __restrict__ out)
{
    extern __shared__ char dsm[];
    char* sbase = (char*)((((uintptr_t)dsm) + 1023) & ~(uintptr_t)1023);
    uint32_t sb = smem_to_u32(sbase);
    const int tid = threadIdx.x;
    const int lid = tid & 31;
    const int wid = tid >> 5;
    const int wm = wid >> 1;
    const int wn = wid & 1;

    const int mBase = blockIdx.y * 128;
    const int nBase = blockIdx.x * 128;

    float acc[2][8][4] = {};
    gemm_mainloop_mma(g_attn, W, mBase, nBase, sbase, sb, acc);

    const int g  = lid >> 2;
    const int t4 = lid & 3;
    #pragma unroll
    for (int i = 0; i < 2; i++) {
        #pragma unroll
        for (int rr = 0; rr < 2; rr++) {
            int t = mBase + wm*32 + i*16 + g + rr*8;
            #pragma unroll
            for (int j = 0; j < 8; j++) {
                int c = nBase + wn*64 + j*8 + 2*t4;
                *(float2*)&out[(size_t)t * ND + c] = make_float2(
                    acc[i][j][rr*2+0] + bias[c],
                    acc[i][j][rr*2+1] + bias[c+1]);
            }
        }
    }
}

// ---------------- tile loaders for attention ---------------------------------
__device__ __forceinline__ void load_tile_T(const float* __restrict__ g, float* s, int tid) {
    int row  = tid >> 2;
    int quad = tid & 3;
    const float4* gp = (const float4*)(g + row * 64);
    #pragma unroll
    for (int seg = 0; seg < 4; seg++) {
        float4 x = gp[quad + seg*4];
        int d0 = (quad + seg*4) * 4;
        s[(d0+0)*68 + row] = x.x;
        s[(d0+1)*68 + row] = x.y;
        s[(d0+2)*68 + row] = x.z;
        s[(d0+3)*68 + row] = x.w;
    }
}
__device__ __forceinline__ void load_tile(const float* __restrict__ g, float* s, int tid) {
    int row  = tid >> 2;
    int quad = tid & 3;
    const float4* gp = (const float4*)(g + row * 64);
    float4* sp = (float4*)(s + row * 68);
    #pragma unroll
    for (int seg = 0; seg < 4; seg++)
        sp[quad + seg*4] = gp[quad + seg*4];
}

// ---------------- K2: causal flash attention (SIMT fp32) ---------------------
__global__ void __launch_bounds__(256) attn_kernel() {
    extern __shared__ float sm[];
    float* Qs = sm;             // [d][row]  64x68
    float* Ks = sm + 64*68;     // [d][col]
    float* Vs = sm + 2*64*68;   // [c][vc]
    float* Ps = sm + 3*64*68;   // [c][row]

    const int tid = threadIdx.x;
    const int tx = tid & 15;
    const int ty = tid >> 4;
    const int bh = blockIdx.y;
    const int q0 = blockIdx.x * 64;

    const float* qbase = g_q + (size_t)bh * (NL*NHD);
    const float* kbase = g_k + (size_t)bh * (NL*NHD);
    const float* vbase = g_v + (size_t)bh * (NL*NHD);

    load_tile_T(qbase + (size_t)q0 * 64, Qs, tid);

    float m[4], lsum[4], O[4][4];
    #pragma unroll
    for (int i = 0; i < 4; i++) {
        m[i] = -1e30f; lsum[i] = 0.f;
        #pragma unroll
        for (int j = 0; j < 4; j++) O[i][j] = 0.f;
    }

    for (int j0 = 0; j0 <= q0; j0 += 64) {
        __syncthreads();
        load_tile_T(kbase + (size_t)j0 * 64, Ks, tid);
        load_tile  (vbase + (size_t)j0 * 64, Vs, tid);
        __syncthreads();

        float s[4][4] = {};
        #pragma unroll 16
        for (int d = 0; d < 64; d++) {
            float4 a4 = *(const float4*)&Qs[d*68 + 4*ty];
            float4 b4 = *(const float4*)&Ks[d*68 + 4*tx];
            float a[4] = {a4.x, a4.y, a4.z, a4.w};
            float b[4] = {b4.x, b4.y, b4.z, b4.w};
            #pragma unroll
            for (int i = 0; i < 4; i++)
                #pragma unroll
                for (int j = 0; j < 4; j++)
                    s[i][j] += a[i] * b[j];
        }
        const float scale = 0.125f;
        if (j0 == q0) {
            #pragma unroll
            for (int i = 0; i < 4; i++)
                #pragma unroll
                for (int j = 0; j < 4; j++) {
                    s[i][j] *= scale;
                    if (j0 + 4*tx + j > q0 + 4*ty + i) s[i][j] = -1e30f;
                }
        } else {
            #pragma unroll
            for (int i = 0; i < 4; i++)
                #pragma unroll
                for (int j = 0; j < 4; j++) s[i][j] *= scale;
        }

        float tm[4];
        #pragma unroll
        for (int i = 0; i < 4; i++)
            tm[i] = fmaxf(fmaxf(s[i][0], s[i][1]), fmaxf(s[i][2], s[i][3]));
        #pragma unroll
        for (int off = 1; off < 16; off <<= 1)
            #pragma unroll
            for (int i = 0; i < 4; i++)
                tm[i] = fmaxf(tm[i], __shfl_xor_sync(0xffffffffu, tm[i], off));

        float alpha[4], rs[4];
        #pragma unroll
        for (int i = 0; i < 4; i++) {
            float mn = fmaxf(m[i], tm[i]);
            alpha[i] = __expf(m[i] - mn);
            m[i] = mn;
            #pragma unroll
            for (int j = 0; j < 4; j++) s[i][j] = __expf(s[i][j] - mn);
            rs[i] = (s[i][0] + s[i][1]) + (s[i][2] + s[i][3]);
        }
        #pragma unroll
        for (int off = 1; off < 16; off <<= 1)
            #pragma unroll
            for (int i = 0; i < 4; i++)
                rs[i] += __shfl_xor_sync(0xffffffffu, rs[i], off);
        #pragma unroll
        for (int i = 0; i < 4; i++) {
            lsum[i] = lsum[i] * alpha[i] + rs[i];
            #pragma unroll
            for (int j = 0; j < 4; j++) O[i][j] *= alpha[i];
        }

        #pragma unroll
        for (int i = 0; i < 4; i++)
            #pragma unroll
            for (int j = 0; j < 4; j++)
                Ps[(4*tx + j)*68 + 4*ty + i] = s[i][j];
        __syncthreads();

        #pragma unroll 16
        for (int c = 0; c < 64; c++) {
            float4 p4 = *(const float4*)&Ps[c*68 + 4*ty];
            float4 v4 = *(const float4*)&Vs[c*68 + 4*tx];
            float p[4] = {p4.x, p4.y, p4.z, p4.w};
            float v[4] = {v4.x, v4.y, v4.z, v4.w};
            #pragma unroll
            for (int i = 0; i < 4; i++)
                #pragma unroll
                for (int j = 0; j < 4; j++)
                    O[i][j] += p[i] * v[j];
        }
    }

    const int b = bh >> 4;
    const int h = bh & 15;
    #pragma unroll
    for (int i = 0; i < 4; i++) {
        float rinv = 1.0f / lsum[i];
        int t = b * NL + q0 + 4*ty + i;
        size_t off = (size_t)t * ND + h*64 + 4*tx;
        *(float4*)&g_attn[off] = make_float4(O[i][0]*rinv, O[i][1]*rinv,
                                             O[i][2]*rinv, O[i][3]*rinv);
    }
}

// ---------------- launch -----------------------------------------------------
extern "C" void kernel_launch(void* const* d_in, const int* in_sizes, int n_in,
                              void* d_out, int out_size) {
    const float* X  = (const float*)d_in[0];
    const float* Wq = (const float*)d_in[1];
    const float* bq = (const float*)d_in[2];
    const float* Wk = (const float*)d_in[3];
    const float* bk = (const float*)d_in[4];
    const float* Wv = (const float*)d_in[5];
    const float* bv = (const float*)d_in[6];
    const float* Wo = (const float*)d_in[7];
    const float* bo = (const float*)d_in[8];
    float* out = (float*)d_out;

    rope_tables_kernel<<<(NL*(NHD/2) + 255)/256, 256>>>();

    cudaFuncSetAttribute(qkv_mma_kernel, cudaFuncAttributeMaxDynamicSharedMemorySize, GEMM_SMEM_BYTES);
    cudaFuncSetAttribute(out_mma_kernel, cudaFuncAttributeMaxDynamicSharedMemorySize, GEMM_SMEM_BYTES);

    qkv_mma_kernel<<<dim3(ND/128, NT/128, 3), 256, GEMM_SMEM_BYTES>>>(X, Wq, bq, Wk, bk, Wv, bv);

    const int attn_smem = 4 * 64 * 68 * (int)sizeof(float);
    cudaFuncSetAttribute(attn_kernel, cudaFuncAttributeMaxDynamicSharedMemorySize, attn_smem);
    attn_kernel<<<dim3(NL/64, NB*NH), 256, attn_smem>>>();

    out_mma_kernel<<<dim3(ND/128, NT/128), 256, GEMM_SMEM_BYTES>>>(Wo, bo, out);
}

// round 9
// speedup vs baseline: 2.2897x; 1.4604x over previous
#include <cuda_runtime.h>
#include <cuda_bf16.h>
#include <stdint.h>
#include <math.h>

#define NB 4
#define NL 2048
#define ND 1024
#define NH 16
#define NHD 64
#define NT (NB*NL)

// ---------------- scratch (device globals: no allocations allowed) ----------
__device__ float g_q[(size_t)NB*NH*NL*NHD];     // [bh][l][hd]
__device__ float g_k[(size_t)NB*NH*NL*NHD];
__device__ float g_v[(size_t)NB*NH*NL*NHD];
__device__ float g_attn[(size_t)NT*ND];         // [t][h*64+hd]
__device__ float g_cos[NL*(NHD/2)];
__device__ float g_sin[NL*(NHD/2)];

// ---------------- helpers ----------------------------------------------------
__device__ __forceinline__ uint32_t smem_to_u32(const void* smem_ptr) {
    uint32_t addr;
    asm("{ .reg .u64 tmp; cvta.to.shared.u64 tmp, %1; cvt.u32.u64 %0, tmp; }"
        : "=r"(addr) : "l"(smem_ptr));
    return addr;
}
#define SWZ(off) ((off) ^ (((off) >> 3) & 0x70))

__device__ __forceinline__ void ldsm4(uint32_t* r, uint32_t a) {
    asm volatile("ldmatrix.sync.aligned.m8n8.x4.shared.b16 {%0,%1,%2,%3}, [%4];"
        : "=r"(r[0]), "=r"(r[1]), "=r"(r[2]), "=r"(r[3]) : "r"(a));
}
__device__ __forceinline__ void ldsm4t(uint32_t* r, uint32_t a) {
    asm volatile("ldmatrix.sync.aligned.m8n8.x4.trans.shared.b16 {%0,%1,%2,%3}, [%4];"
        : "=r"(r[0]), "=r"(r[1]), "=r"(r[2]), "=r"(r[3]) : "r"(a));
}
__device__ __forceinline__ void mma16816(float* c, const uint32_t* a,
                                         uint32_t b0, uint32_t b1) {
    asm volatile(
        "mma.sync.aligned.m16n8k16.row.col.f32.bf16.bf16.f32 "
        "{%0,%1,%2,%3}, {%4,%5,%6,%7}, {%8,%9}, {%0,%1,%2,%3};"
        : "+f"(c[0]), "+f"(c[1]), "+f"(c[2]), "+f"(c[3])
        : "r"(a[0]), "r"(a[1]), "r"(a[2]), "r"(a[3]), "r"(b0), "r"(b1));
}
// hi/lo bf16 split of a float pair, packed as bf16x2
__device__ __forceinline__ void split2(float a, float b, uint32_t& hi, uint32_t& lo) {
    __nv_bfloat162 h, l;
    h.x = __float2bfloat16(a); h.y = __float2bfloat16(b);
    l.x = __float2bfloat16(a - __bfloat162float(h.x));
    l.y = __float2bfloat16(b - __bfloat162float(h.y));
    hi = *(uint32_t*)&h; lo = *(uint32_t*)&l;
}

// SMEM layout (bytes, relative to 1024-aligned base) for GEMM kernels
#define SOFF_AH 0
#define SOFF_AL 16384
#define SOFF_BH 32768
#define SOFF_BL 49152
#define GEMM_SMEM_BYTES (65536 + 1024)

// ---------------- K0: RoPE tables (fp64 for accuracy) ------------------------
__global__ void rope_tables_kernel() {
    int idx = blockIdx.x * 256 + threadIdx.x;
    if (idx >= NL * (NHD/2)) return;
    int l = idx >> 5;
    int i = idx & 31;
    double inv = exp(-((double)(2*i) / (double)NHD) * log(10000.0));
    double a = (double)l * inv;
    g_cos[idx] = (float)cos(a);
    g_sin[idx] = (float)sin(a);
}

// ---------------- bf16 hi/lo split store into swizzled smem ------------------
__device__ __forceinline__ void cvt_store(char* sh, char* sl, int r, int f4, float4 x) {
    uint32_t h01, h23, l01, l23;
    split2(x.x, x.y, h01, l01);
    split2(x.z, x.w, h23, l23);
    uint32_t off = (uint32_t)(r * 128 + f4 * 8);
    uint32_t sw = SWZ(off);
    *(uint2*)(sh + sw) = make_uint2(h01, h23);
    *(uint2*)(sl + sw) = make_uint2(l01, l23);
}

// ---------------- shared GEMM mainloop: acc = A[m,:] * B[n,:]^T --------------
__device__ __forceinline__ void gemm_mainloop_mma(
    const float* __restrict__ Amat, const float* __restrict__ Bmat,
    int mBase, int nBase, char* sbase, uint32_t sb, float acc[2][8][4])
{
    const int tid = threadIdx.x;
    const int lid = tid & 31;
    const int wid = tid >> 5;
    const int wm = wid >> 1;
    const int wn = wid & 1;
    const int f4 = tid & 15;
    const int r0 = tid >> 4;

    char* sAh = sbase + SOFF_AH;
    char* sAl = sbase + SOFF_AL;
    char* sBh = sbase + SOFF_BH;
    char* sBl = sbase + SOFF_BL;

    const int a_row = wm*32 + (lid & 7) + ((lid >> 3) & 1) * 8;
    const int a_cb  = (lid >> 4) * 8;
    const int b_row = wn*64 + (lid & 7) + ((lid >> 4) & 1) * 8;
    const int b_cb  = ((lid >> 3) & 1) * 8;

    for (int stage = 0; stage < ND/64; stage++) {
        const int k0g = stage * 64;
        float4 xa[8], xb[8];
        #pragma unroll
        for (int rr = 0; rr < 8; rr++) {
            int r = rr * 16 + r0;
            xa[rr] = *(const float4*)(Amat + (size_t)(mBase + r) * ND + k0g + f4*4);
            xb[rr] = *(const float4*)(Bmat + (size_t)(nBase + r) * ND + k0g + f4*4);
        }
        __syncthreads();
        #pragma unroll
        for (int rr = 0; rr < 8; rr++) {
            int r = rr * 16 + r0;
            cvt_store(sAh, sAl, r, f4, xa[rr]);
            cvt_store(sBh, sBl, r, f4, xb[rr]);
        }
        __syncthreads();

        #pragma unroll
        for (int ks = 0; ks < 4; ks++) {
            const int k0 = ks * 16;
            uint32_t ah[2][4], al[2][4], bh[4][4], bl[4][4];
            #pragma unroll
            for (int i = 0; i < 2; i++) {
                uint32_t off = (uint32_t)((a_row + i*16) * 128 + (k0 + a_cb) * 2);
                uint32_t sw = SWZ(off);
                ldsm4(ah[i], sb + SOFF_AH + sw);
                ldsm4(al[i], sb + SOFF_AL + sw);
            }
            #pragma unroll
            for (int jj = 0; jj < 4; jj++) {
                uint32_t off = (uint32_t)((b_row + jj*16) * 128 + (k0 + b_cb) * 2);
                uint32_t sw = SWZ(off);
                ldsm4(bh[jj], sb + SOFF_BH + sw);
                ldsm4(bl[jj], sb + SOFF_BL + sw);
            }
            #pragma unroll
            for (int i = 0; i < 2; i++)
                #pragma unroll
                for (int jj = 0; jj < 4; jj++) {
                    mma16816(acc[i][2*jj],   ah[i], bh[jj][0], bh[jj][1]);
                    mma16816(acc[i][2*jj+1], ah[i], bh[jj][2], bh[jj][3]);
                    mma16816(acc[i][2*jj],   ah[i], bl[jj][0], bl[jj][1]);
                    mma16816(acc[i][2*jj+1], ah[i], bl[jj][2], bl[jj][3]);
                    mma16816(acc[i][2*jj],   al[i], bh[jj][0], bh[jj][1]);
                    mma16816(acc[i][2*jj+1], al[i], bh[jj][2], bh[jj][3]);
                }
        }
    }
}

// ---------------- K1: fused QKV projection + RoPE (mma.sync) -----------------
__global__ void __launch_bounds__(256, 1)
qkv_mma_kernel(const float* __restrict__ X,
               const float* __restrict__ Wq, const float* __restrict__ bq,
               const float* __restrict__ Wk, const float* __restrict__ bk,
               const float* __restrict__ Wv, const float* __restrict__ bv)
{
    extern __shared__ char dsm[];
    char* sbase = (char*)((((uintptr_t)dsm) + 1023) & ~(uintptr_t)1023);
    uint32_t sb = smem_to_u32(sbase);
    const int tid = threadIdx.x;
    const int lid = tid & 31;
    const int wid = tid >> 5;
    const int wm = wid >> 1;
    const int wn = wid & 1;

    const int z = blockIdx.z;
    const float* W    = (z == 0) ? Wq : (z == 1) ? Wk : Wv;
    const float* bias = (z == 0) ? bq : (z == 1) ? bk : bv;
    float* dst        = (z == 0) ? g_q : (z == 1) ? g_k : g_v;

    const int mBase = blockIdx.y * 128;
    const int nBase = blockIdx.x * 128;

    float acc[2][8][4] = {};
    gemm_mainloop_mma(X, W, mBase, nBase, sbase, sb, acc);

    const int g  = lid >> 2;
    const int t4 = lid & 3;
    #pragma unroll
    for (int i = 0; i < 2; i++) {
        #pragma unroll
        for (int rr = 0; rr < 2; rr++) {
            int t = mBase + wm*32 + i*16 + g + rr*8;
            int b = t >> 11;
            int l = t & (NL - 1);
            #pragma unroll
            for (int j = 0; j < 8; j++) {
                int c = nBase + wn*64 + j*8 + 2*t4;
                float y0 = acc[i][j][rr*2+0] + bias[c];
                float y1 = acc[i][j][rr*2+1] + bias[c+1];
                if (z < 2) {
                    int p0 = (c & 63) >> 1;
                    float co = g_cos[l*32 + p0], si = g_sin[l*32 + p0];
                    float e = y0, o = y1;
                    y0 = e*co - o*si;
                    y1 = e*si + o*co;
                }
                int h  = c >> 6;
                int hd = c & 63;
                size_t off = (((size_t)(b*NH + h))*NL + l)*NHD + hd;
                *(float2*)&dst[off] = make_float2(y0, y1);
            }
        }
    }
}

// ---------------- K3: output projection (mma.sync) ---------------------------
__global__ void __launch_bounds__(256, 1)
out_mma_kernel(const float* __restrict__ W, const float* __restrict__ bias,
               float* __restrict__ out)
{
    extern __shared__ char dsm[];
    char* sbase = (char*)((((uintptr_t)dsm) + 1023) & ~(uintptr_t)1023);
    uint32_t sb = smem_to_u32(sbase);
    const int tid = threadIdx.x;
    const int lid = tid & 31;
    const int wid = tid >> 5;
    const int wm = wid >> 1;
    const int wn = wid & 1;

    const int mBase = blockIdx.y * 128;
    const int nBase = blockIdx.x * 128;

    float acc[2][8][4] = {};
    gemm_mainloop_mma(g_attn, W, mBase, nBase, sbase, sb, acc);

    const int g  = lid >> 2;
    const int t4 = lid & 3;
    #pragma unroll
    for (int i = 0; i < 2; i++) {
        #pragma unroll
        for (int rr = 0; rr < 2; rr++) {
            int t = mBase + wm*32 + i*16 + g + rr*8;
            #pragma unroll
            for (int j = 0; j < 8; j++) {
                int c = nBase + wn*64 + j*8 + 2*t4;
                *(float2*)&out[(size_t)t * ND + c] = make_float2(
                    acc[i][j][rr*2+0] + bias[c],
                    acc[i][j][rr*2+1] + bias[c+1]);
            }
        }
    }
}

// ======================= K2: flash attention (mma.sync) ======================
// smem offsets for the 128x64 bf16 tiles (each 16 KB)
#define AOFF_KH 0
#define AOFF_KL 16384
#define AOFF_VH 32768
#define AOFF_VL 49152
#define ATT_SMEM_BYTES (65536 + 1024)

// convert a [128 x 64] fp32 tile (row stride 64) into hi/lo bf16 swizzled smem
__device__ __forceinline__ void cvt_tile_128x64(const float* __restrict__ g,
                                                char* sh, char* sl, int tid) {
    const int r  = tid >> 1;
    const int c0 = (tid & 1) * 8;
    const float4* gp = (const float4*)(g + (size_t)r * 64);
    #pragma unroll
    for (int i = 0; i < 8; i++) {
        float4 x = gp[c0 + i];
        uint32_t h01, h23, l01, l23;
        split2(x.x, x.y, h01, l01);
        split2(x.z, x.w, h23, l23);
        uint32_t sw = SWZ((uint32_t)(r * 128 + (c0 + i) * 8));
        *(uint2*)(sh + sw) = make_uint2(h01, h23);
        *(uint2*)(sl + sw) = make_uint2(l01, l23);
    }
}

// grid (NL/128, NB*NH), 256 threads. CTA: 128 query rows of one (b,h).
// 8 warps, warp w owns query rows [w*16, w*16+16).
__global__ void __launch_bounds__(256, 1) attn_mma_kernel() {
    extern __shared__ char dsm[];
    char* sbase = (char*)((((uintptr_t)dsm) + 1023) & ~(uintptr_t)1023);
    uint32_t sb = smem_to_u32(sbase);

    const int tid = threadIdx.x;
    const int lid = tid & 31;
    const int wid = tid >> 5;
    const int bh = blockIdx.y;
    const int qt = (int)gridDim.x - 1 - (int)blockIdx.x;   // heavy tiles first
    const int q0 = qt * 128;

    const float* qg = g_q + (size_t)bh * (NL*NHD);
    const float* kg = g_k + (size_t)bh * (NL*NHD);
    const float* vg = g_v + (size_t)bh * (NL*NHD);

    // ---- stage Q through the K buffers, load Q fragments (hi/lo) ----
    cvt_tile_128x64(qg + (size_t)q0 * 64, sbase + AOFF_KH, sbase + AOFF_KL, tid);
    __syncthreads();
    const int a_row = wid*16 + (lid & 7) + ((lid >> 3) & 1) * 8;
    const int a_cb  = (lid >> 4) * 8;
    uint32_t Qh[4][4], Ql[4][4];
    #pragma unroll
    for (int kb = 0; kb < 4; kb++) {
        uint32_t sw = SWZ((uint32_t)(a_row * 128 + (kb*16 + a_cb) * 2));
        ldsm4(Qh[kb], sb + AOFF_KH + sw);
        ldsm4(Ql[kb], sb + AOFF_KL + sw);
    }

    // per-lane softmax state: rows g and g+8 of the warp's 16 rows
    const int g  = lid >> 2;
    const int t4 = lid & 3;
    float m0 = -1e30f, m1 = -1e30f, l0 = 0.f, l1 = 0.f;
    float O[8][4] = {};

    const int b_row = (lid & 7) + ((lid >> 4) & 1) * 8;
    const int b_cb  = ((lid >> 3) & 1) * 8;
    const int v_row = (lid & 7) + ((lid >> 3) & 1) * 8;
    const int v_col = ((lid >> 4) & 1) * 8;
    const int qrow0 = q0 + wid*16 + g;       // lane's first query row

    for (int kt = 0; kt <= qt; kt++) {
        __syncthreads();
        cvt_tile_128x64(kg + (size_t)kt * 128 * 64, sbase + AOFF_KH, sbase + AOFF_KL, tid);
        cvt_tile_128x64(vg + (size_t)kt * 128 * 64, sbase + AOFF_VH, sbase + AOFF_VL, tid);
        __syncthreads();

        // ---- S = Q K^T (3-term compensated) ----
        float sacc[16][4] = {};
        #pragma unroll
        for (int kb = 0; kb < 4; kb++) {
            #pragma unroll
            for (int jj = 0; jj < 8; jj++) {
                uint32_t kh[4], kl[4];
                uint32_t sw = SWZ((uint32_t)((jj*16 + b_row) * 128 + (kb*16 + b_cb) * 2));
                ldsm4(kh, sb + AOFF_KH + sw);
                ldsm4(kl, sb + AOFF_KL + sw);
                mma16816(sacc[2*jj],   Qh[kb], kh[0], kh[1]);
                mma16816(sacc[2*jj+1], Qh[kb], kh[2], kh[3]);
                mma16816(sacc[2*jj],   Ql[kb], kh[0], kh[1]);
                mma16816(sacc[2*jj+1], Ql[kb], kh[2], kh[3]);
                mma16816(sacc[2*jj],   Qh[kb], kl[0], kl[1]);
                mma16816(sacc[2*jj+1], Qh[kb], kl[2], kl[3]);
            }
        }

        // ---- scale (+causal mask on the diagonal tile) ----
        const float scale = 0.125f;
        if (kt == qt) {
            #pragma unroll
            for (int j = 0; j < 16; j++) {
                int col = kt*128 + j*8 + 2*t4;
                #pragma unroll
                for (int e = 0; e < 4; e++) {
                    int c = col + (e & 1);
                    int r = qrow0 + (e >> 1) * 8;
                    sacc[j][e] = (c > r) ? -1e30f : sacc[j][e] * scale;
                }
            }
        } else {
            #pragma unroll
            for (int j = 0; j < 16; j++)
                #pragma unroll
                for (int e = 0; e < 4; e++) sacc[j][e] *= scale;
        }

        // ---- online softmax (rows live in quads: shfl_xor 1,2) ----
        float mx0 = -1e30f, mx1 = -1e30f;
        #pragma unroll
        for (int j = 0; j < 16; j++) {
            mx0 = fmaxf(mx0, fmaxf(sacc[j][0], sacc[j][1]));
            mx1 = fmaxf(mx1, fmaxf(sacc[j][2], sacc[j][3]));
        }
        mx0 = fmaxf(mx0, __shfl_xor_sync(0xffffffffu, mx0, 1));
        mx0 = fmaxf(mx0, __shfl_xor_sync(0xffffffffu, mx0, 2));
        mx1 = fmaxf(mx1, __shfl_xor_sync(0xffffffffu, mx1, 1));
        mx1 = fmaxf(mx1, __shfl_xor_sync(0xffffffffu, mx1, 2));

        float mn0 = fmaxf(m0, mx0), mn1 = fmaxf(m1, mx1);
        float al0 = __expf(m0 - mn0), al1 = __expf(m1 - mn1);
        m0 = mn0; m1 = mn1;

        float rs0 = 0.f, rs1 = 0.f;
        #pragma unroll
        for (int j = 0; j < 16; j++) {
            sacc[j][0] = __expf(sacc[j][0] - mn0);
            sacc[j][1] = __expf(sacc[j][1] - mn0);
            sacc[j][2] = __expf(sacc[j][2] - mn1);
            sacc[j][3] = __expf(sacc[j][3] - mn1);
            rs0 += sacc[j][0] + sacc[j][1];
            rs1 += sacc[j][2] + sacc[j][3];
        }
        rs0 += __shfl_xor_sync(0xffffffffu, rs0, 1);
        rs0 += __shfl_xor_sync(0xffffffffu, rs0, 2);
        rs1 += __shfl_xor_sync(0xffffffffu, rs1, 1);
        rs1 += __shfl_xor_sync(0xffffffffu, rs1, 2);
        l0 = l0 * al0 + rs0;
        l1 = l1 * al1 + rs1;
        #pragma unroll
        for (int j = 0; j < 8; j++) {
            O[j][0] *= al0; O[j][1] *= al0;
            O[j][2] *= al1; O[j][3] *= al1;
        }

        // ---- O += P V (3-term compensated; P frags straight from sacc) ----
        #pragma unroll
        for (int kb2 = 0; kb2 < 8; kb2++) {
            uint32_t ph[4], pl[4];
            split2(sacc[2*kb2][0],   sacc[2*kb2][1],   ph[0], pl[0]);
            split2(sacc[2*kb2][2],   sacc[2*kb2][3],   ph[1], pl[1]);
            split2(sacc[2*kb2+1][0], sacc[2*kb2+1][1], ph[2], pl[2]);
            split2(sacc[2*kb2+1][2], sacc[2*kb2+1][3], ph[3], pl[3]);
            #pragma unroll
            for (int nn = 0; nn < 4; nn++) {
                uint32_t vh[4], vl[4];
                uint32_t sw = SWZ((uint32_t)((kb2*16 + v_row) * 128 + (nn*16 + v_col) * 2));
                ldsm4t(vh, sb + AOFF_VH + sw);
                ldsm4t(vl, sb + AOFF_VL + sw);
                mma16816(O[2*nn],   ph, vh[0], vh[1]);
                mma16816(O[2*nn+1], ph, vh[2], vh[3]);
                mma16816(O[2*nn],   pl, vh[0], vh[1]);
                mma16816(O[2*nn+1], pl, vh[2], vh[3]);
                mma16816(O[2*nn],   ph, vl[0], vl[1]);
                mma16816(O[2*nn+1], ph, vl[2], vl[3]);
            }
        }
    }

    // ---- epilogue: normalize and write [t][h*64+hd] ----
    float r0 = 1.0f / l0, r1 = 1.0f / l1;
    const int bb = bh >> 4;
    const int hh = bh & 15;
    const int t0 = bb * NL + qrow0;
    #pragma unroll
    for (int j = 0; j < 8; j++) {
        int hd = hh*64 + j*8 + 2*t4;
        *(float2*)&g_attn[(size_t)t0 * ND + hd] =
            make_float2(O[j][0]*r0, O[j][1]*r0);
        *(float2*)&g_attn[(size_t)(t0 + 8) * ND + hd] =
            make_float2(O[j][2]*r1, O[j][3]*r1);
    }
}

// ---------------- launch -----------------------------------------------------
extern "C" void kernel_launch(void* const* d_in, const int* in_sizes, int n_in,
                              void* d_out, int out_size) {
    const float* X  = (const float*)d_in[0];
    const float* Wq = (const float*)d_in[1];
    const float* bq = (const float*)d_in[2];
    const float* Wk = (const float*)d_in[3];
    const float* bk = (const float*)d_in[4];
    const float* Wv = (const float*)d_in[5];
    const float* bv = (const float*)d_in[6];
    const float* Wo = (const float*)d_in[7];
    const float* bo = (const float*)d_in[8];
    float* out = (float*)d_out;

    rope_tables_kernel<<<(NL*(NHD/2) + 255)/256, 256>>>();

    cudaFuncSetAttribute(qkv_mma_kernel, cudaFuncAttributeMaxDynamicSharedMemorySize, GEMM_SMEM_BYTES);
    cudaFuncSetAttribute(out_mma_kernel, cudaFuncAttributeMaxDynamicSharedMemorySize, GEMM_SMEM_BYTES);
    cudaFuncSetAttribute(attn_mma_kernel, cudaFuncAttributeMaxDynamicSharedMemorySize, ATT_SMEM_BYTES);

    qkv_mma_kernel<<<dim3(ND/128, NT/128, 3), 256, GEMM_SMEM_BYTES>>>(X, Wq, bq, Wk, bk, Wv, bv);

    attn_mma_kernel<<<dim3(NL/128, NB*NH), 256, ATT_SMEM_BYTES>>>();

    out_mma_kernel<<<dim3(ND/128, NT/128), 256, GEMM_SMEM_BYTES>>>(Wo, bo, out);
}

// round 10
// speedup vs baseline: 3.2089x; 1.4014x over previous
#include <cuda_runtime.h>
#include <cuda_bf16.h>
#include <stdint.h>
#include <math.h>

#define NB 4
#define NL 2048
#define ND 1024
#define NH 16
#define NHD 64
#define NT (NB*NL)

// ---------------- scratch (device globals: no allocations allowed) ----------
// hi/lo bf16 split operands
__device__ __nv_bfloat16 g_xh[(size_t)NT*ND];
__device__ __nv_bfloat16 g_xl[(size_t)NT*ND];
__device__ __nv_bfloat16 g_wh[(size_t)4*ND*ND];   // Wq,Wk,Wv,Wo
__device__ __nv_bfloat16 g_wl[(size_t)4*ND*ND];
__device__ __nv_bfloat16 g_qh[(size_t)NB*NH*NL*NHD];  // [bh][l][hd]
__device__ __nv_bfloat16 g_ql[(size_t)NB*NH*NL*NHD];
__device__ __nv_bfloat16 g_kh[(size_t)NB*NH*NL*NHD];
__device__ __nv_bfloat16 g_kl[(size_t)NB*NH*NL*NHD];
__device__ __nv_bfloat16 g_vh[(size_t)NB*NH*NL*NHD];
__device__ __nv_bfloat16 g_vl[(size_t)NB*NH*NL*NHD];
__device__ __nv_bfloat16 g_ah[(size_t)NT*ND];     // attention out [t][h*64+hd]
__device__ __nv_bfloat16 g_al[(size_t)NT*ND];
__device__ float g_cos[NL*(NHD/2)];
__device__ float g_sin[NL*(NHD/2)];

// ---------------- helpers ----------------------------------------------------
__device__ __forceinline__ uint32_t smem_to_u32(const void* smem_ptr) {
    uint32_t addr;
    asm("{ .reg .u64 tmp; cvta.to.shared.u64 tmp, %1; cvt.u32.u64 %0, tmp; }"
        : "=r"(addr) : "l"(smem_ptr));
    return addr;
}
#define SWZ(off) ((off) ^ (((off) >> 3) & 0x70))

__device__ __forceinline__ void ldsm4(uint32_t* r, uint32_t a) {
    asm volatile("ldmatrix.sync.aligned.m8n8.x4.shared.b16 {%0,%1,%2,%3}, [%4];"
        : "=r"(r[0]), "=r"(r[1]), "=r"(r[2]), "=r"(r[3]) : "r"(a));
}
__device__ __forceinline__ void ldsm4t(uint32_t* r, uint32_t a) {
    asm volatile("ldmatrix.sync.aligned.m8n8.x4.trans.shared.b16 {%0,%1,%2,%3}, [%4];"
        : "=r"(r[0]), "=r"(r[1]), "=r"(r[2]), "=r"(r[3]) : "r"(a));
}
__device__ __forceinline__ void mma16816(float* c, const uint32_t* a,
                                         uint32_t b0, uint32_t b1) {
    asm volatile(
        "mma.sync.aligned.m16n8k16.row.col.f32.bf16.bf16.f32 "
        "{%0,%1,%2,%3}, {%4,%5,%6,%7}, {%8,%9}, {%0,%1,%2,%3};"
        : "+f"(c[0]), "+f"(c[1]), "+f"(c[2]), "+f"(c[3])
        : "r"(a[0]), "r"(a[1]), "r"(a[2]), "r"(a[3]), "r"(b0), "r"(b1));
}
__device__ __forceinline__ void split2(float a, float b, uint32_t& hi, uint32_t& lo) {
    __nv_bfloat162 h, l;
    h.x = __float2bfloat16(a); h.y = __float2bfloat16(b);
    l.x = __float2bfloat16(a - __bfloat162float(h.x));
    l.y = __float2bfloat16(b - __bfloat162float(h.y));
    hi = *(uint32_t*)&h; lo = *(uint32_t*)&l;
}
__device__ __forceinline__ void cp_async16(uint32_t sdst, const void* gsrc) {
    asm volatile("cp.async.cg.shared.global [%0], [%1], 16;"
        :: "r"(sdst), "l"(gsrc));
}
#define CP_COMMIT() asm volatile("cp.async.commit_group;" ::: "memory")
#define CP_WAIT(n)  asm volatile("cp.async.wait_group %0;" :: "n"(n) : "memory")

// copy one [128 x 64] bf16 tile (row stride gstride elems) into swizzled smem
__device__ __forceinline__ void cp_tile(uint32_t sdst, const __nv_bfloat16* gsrc,
                                        int gstride, int tid) {
    #pragma unroll
    for (int it = 0; it < 4; it++) {
        int idx = tid + it * 256;          // 0..1023
        int row = idx >> 3, seg = idx & 7;
        cp_async16(sdst + SWZ((uint32_t)(row * 128 + seg * 16)),
                   gsrc + (size_t)row * gstride + seg * 8);
    }
}

// ---------------- K0a: RoPE tables (fp64 for accuracy) -----------------------
__global__ void rope_tables_kernel() {
    int idx = blockIdx.x * 256 + threadIdx.x;
    if (idx >= NL * (NHD/2)) return;
    int l = idx >> 5;
    int i = idx & 31;
    double inv = exp(-((double)(2*i) / (double)NHD) * log(10000.0));
    double a = (double)l * inv;
    g_cos[idx] = (float)cos(a);
    g_sin[idx] = (float)sin(a);
}

// ---------------- K0b: fp32 -> hi/lo bf16 converter --------------------------
__global__ void cvt_kernel(const float* __restrict__ src,
                           __nv_bfloat16* __restrict__ dh,
                           __nv_bfloat16* __restrict__ dl, int n4) {
    int i = blockIdx.x * 256 + threadIdx.x;
    if (i >= n4) return;
    float4 x = ((const float4*)src)[i];
    uint32_t h01, h23, l01, l23;
    split2(x.x, x.y, h01, l01);
    split2(x.z, x.w, h23, l23);
    ((uint2*)dh)[i] = make_uint2(h01, h23);
    ((uint2*)dl)[i] = make_uint2(l01, l23);
}

// ---------------- GEMM mainloop (bf16 operands, cp.async 2-stage) ------------
// smem stage block 64KB: {AH:0, AL:16K, BH:32K, BL:48K}; stages at 0 / 65536
#define GEMM_SMEM_BYTES (2*65536 + 1024)

__device__ __forceinline__ void gemm_issue(
    uint32_t sb, int s, const __nv_bfloat16* Ah, const __nv_bfloat16* Al,
    const __nv_bfloat16* Bh, const __nv_bfloat16* Bl, int tid)
{
    uint32_t st = sb + (uint32_t)(s & 1) * 65536;
    int k0 = s * 64;
    cp_tile(st + 0,     Ah + k0, ND, tid);
    cp_tile(st + 16384, Al + k0, ND, tid);
    cp_tile(st + 32768, Bh + k0, ND, tid);
    cp_tile(st + 49152, Bl + k0, ND, tid);
    CP_COMMIT();
}

__device__ __forceinline__ void gemm_mainloop_bf16(
    const __nv_bfloat16* __restrict__ Ah, const __nv_bfloat16* __restrict__ Al,
    const __nv_bfloat16* __restrict__ Bh, const __nv_bfloat16* __restrict__ Bl,
    uint32_t sb, float acc[2][8][4])
{
    const int tid = threadIdx.x;
    const int lid = tid & 31;
    const int wid = tid >> 5;
    const int wm = wid >> 1;
    const int wn = wid & 1;

    const int a_row = wm*32 + (lid & 7) + ((lid >> 3) & 1) * 8;
    const int a_cb  = (lid >> 4) * 8;
    const int b_row = wn*64 + (lid & 7) + ((lid >> 4) & 1) * 8;
    const int b_cb  = ((lid >> 3) & 1) * 8;

    gemm_issue(sb, 0, Ah, Al, Bh, Bl, tid);
    for (int s = 0; s < ND/64; s++) {
        if (s + 1 < ND/64) {
            gemm_issue(sb, s + 1, Ah, Al, Bh, Bl, tid);
            CP_WAIT(1);
        } else {
            CP_WAIT(0);
        }
        __syncthreads();
        uint32_t st = sb + (uint32_t)(s & 1) * 65536;

        #pragma unroll
        for (int ks = 0; ks < 4; ks++) {
            const int k0 = ks * 16;
            uint32_t ah[2][4], al[2][4], bh[4][4], bl[4][4];
            #pragma unroll
            for (int i = 0; i < 2; i++) {
                uint32_t sw = SWZ((uint32_t)((a_row + i*16) * 128 + (k0 + a_cb) * 2));
                ldsm4(ah[i], st + 0 + sw);
                ldsm4(al[i], st + 16384 + sw);
            }
            #pragma unroll
            for (int jj = 0; jj < 4; jj++) {
                uint32_t sw = SWZ((uint32_t)((b_row + jj*16) * 128 + (k0 + b_cb) * 2));
                ldsm4(bh[jj], st + 32768 + sw);
                ldsm4(bl[jj], st + 49152 + sw);
            }
            #pragma unroll
            for (int i = 0; i < 2; i++)
                #pragma unroll
                for (int jj = 0; jj < 4; jj++) {
                    mma16816(acc[i][2*jj],   ah[i], bh[jj][0], bh[jj][1]);
                    mma16816(acc[i][2*jj+1], ah[i], bh[jj][2], bh[jj][3]);
                    mma16816(acc[i][2*jj],   ah[i], bl[jj][0], bl[jj][1]);
                    mma16816(acc[i][2*jj+1], ah[i], bl[jj][2], bl[jj][3]);
                    mma16816(acc[i][2*jj],   al[i], bh[jj][0], bh[jj][1]);
                    mma16816(acc[i][2*jj+1], al[i], bh[jj][2], bh[jj][3]);
                }
        }
        __syncthreads();
    }
}

// ---------------- K1: fused QKV projection + RoPE ----------------------------
__global__ void __launch_bounds__(256, 1)
qkv_mma_kernel()
{
    extern __shared__ char dsm[];
    char* sbase = (char*)((((uintptr_t)dsm) + 1023) & ~(uintptr_t)1023);
    uint32_t sb = smem_to_u32(sbase);
    const int tid = threadIdx.x;
    const int lid = tid & 31;
    const int wid = tid >> 5;
    const int wm = wid >> 1;
    const int wn = wid & 1;

    const int z = blockIdx.z;
    __nv_bfloat16* dsth = (z == 0) ? g_qh : (z == 1) ? g_kh : g_vh;
    __nv_bfloat16* dstl = (z == 0) ? g_ql : (z == 1) ? g_kl : g_vl;

    const int mBase = blockIdx.y * 128;
    const int nBase = blockIdx.x * 128;

    float acc[2][8][4] = {};
    gemm_mainloop_bf16(g_xh + (size_t)mBase * ND, g_xl + (size_t)mBase * ND,
                       g_wh + (size_t)z * ND * ND + (size_t)nBase * ND,
                       g_wl + (size_t)z * ND * ND + (size_t)nBase * ND,
                       sb, acc);

    // bias lives in constant-ish global via kernel params? biases passed via launch:
    // (biases fetched from global args bound in launcher through __constant__ stand-in)
    // -> instead: bias pointers passed in via grid-constant globals below.
    extern __device__ float* g_bias_ptrs[4];   // set by launcher? not allowed; use params
    (void)g_bias_ptrs;
    // NOTE: bias handled in epilogue via parameterless path replaced below.
    // (real implementation: bias passed through kernel arguments — see launcher)
}

// The above placeholder is unused; real kernels take bias via arguments:
__global__ void __launch_bounds__(256, 1)
qkv_mma_kernel2(const float* __restrict__ bq, const float* __restrict__ bk,
                const float* __restrict__ bv)
{
    extern __shared__ char dsm[];
    char* sbase = (char*)((((uintptr_t)dsm) + 1023) & ~(uintptr_t)1023);
    uint32_t sb = smem_to_u32(sbase);
    const int tid = threadIdx.x;
    const int lid = tid & 31;
    const int wid = tid >> 5;
    const int wm = wid >> 1;
    const int wn = wid & 1;

    const int z = blockIdx.z;
    const float* bias = (z == 0) ? bq : (z == 1) ? bk : bv;
    __nv_bfloat16* dsth = (z == 0) ? g_qh : (z == 1) ? g_kh : g_vh;
    __nv_bfloat16* dstl = (z == 0) ? g_ql : (z == 1) ? g_kl : g_vl;

    const int mBase = blockIdx.y * 128;
    const int nBase = blockIdx.x * 128;

    float acc[2][8][4] = {};
    gemm_mainloop_bf16(g_xh + (size_t)mBase * ND, g_xl + (size_t)mBase * ND,
                       g_wh + (size_t)z * ND * ND + (size_t)nBase * ND,
                       g_wl + (size_t)z * ND * ND + (size_t)nBase * ND,
                       sb, acc);

    const int g  = lid >> 2;
    const int t4 = lid & 3;
    #pragma unroll
    for (int i = 0; i < 2; i++) {
        #pragma unroll
        for (int rr = 0; rr < 2; rr++) {
            int t = mBase + wm*32 + i*16 + g + rr*8;
            int b = t >> 11;
            int l = t & (NL - 1);
            #pragma unroll
            for (int j = 0; j < 8; j++) {
                int c = nBase + wn*64 + j*8 + 2*t4;
                float y0 = acc[i][j][rr*2+0] + bias[c];
                float y1 = acc[i][j][rr*2+1] + bias[c+1];
                if (z < 2) {
                    int p0 = (c & 63) >> 1;
                    float co = g_cos[l*32 + p0], si = g_sin[l*32 + p0];
                    float e = y0, o = y1;
                    y0 = e*co - o*si;
                    y1 = e*si + o*co;
                }
                int h  = c >> 6;
                int hd = c & 63;
                size_t idx = (((size_t)(b*NH + h))*NL + l)*NHD + hd;
                uint32_t hi, lo;
                split2(y0, y1, hi, lo);
                *(uint32_t*)&dsth[idx] = hi;
                *(uint32_t*)&dstl[idx] = lo;
            }
        }
    }
}

// ---------------- K3: output projection --------------------------------------
__global__ void __launch_bounds__(256, 1)
out_mma_kernel(const float* __restrict__ bias, float* __restrict__ out)
{
    extern __shared__ char dsm[];
    char* sbase = (char*)((((uintptr_t)dsm) + 1023) & ~(uintptr_t)1023);
    uint32_t sb = smem_to_u32(sbase);
    const int tid = threadIdx.x;
    const int lid = tid & 31;
    const int wid = tid >> 5;
    const int wm = wid >> 1;
    const int wn = wid & 1;

    const int mBase = blockIdx.y * 128;
    const int nBase = blockIdx.x * 128;

    float acc[2][8][4] = {};
    gemm_mainloop_bf16(g_ah + (size_t)mBase * ND, g_al + (size_t)mBase * ND,
                       g_wh + (size_t)3 * ND * ND + (size_t)nBase * ND,
                       g_wl + (size_t)3 * ND * ND + (size_t)nBase * ND,
                       sb, acc);

    const int g  = lid >> 2;
    const int t4 = lid & 3;
    #pragma unroll
    for (int i = 0; i < 2; i++) {
        #pragma unroll
        for (int rr = 0; rr < 2; rr++) {
            int t = mBase + wm*32 + i*16 + g + rr*8;
            #pragma unroll
            for (int j = 0; j < 8; j++) {
                int c = nBase + wn*64 + j*8 + 2*t4;
                *(float2*)&out[(size_t)t * ND + c] = make_float2(
                    acc[i][j][rr*2+0] + bias[c],
                    acc[i][j][rr*2+1] + bias[c+1]);
            }
        }
    }
}

// ======================= K2: flash attention (bf16 + cp.async) ===============
// stage block 64KB: {KH:0, KL:16K, VH:32K, VL:48K}; stages at 0 / 65536
#define ATT_SMEM_BYTES (2*65536 + 1024)

__device__ __forceinline__ void attn_issue(uint32_t sb, int kt, int buf,
                                           const __nv_bfloat16* kh, const __nv_bfloat16* kl,
                                           const __nv_bfloat16* vh, const __nv_bfloat16* vl,
                                           int tid) {
    uint32_t st = sb + (uint32_t)buf * 65536;
    size_t off = (size_t)kt * 128 * NHD;
    cp_tile(st + 0,     kh + off, NHD, tid);
    cp_tile(st + 16384, kl + off, NHD, tid);
    cp_tile(st + 32768, vh + off, NHD, tid);
    cp_tile(st + 49152, vl + off, NHD, tid);
    CP_COMMIT();
}

// grid (NL/128, NB*NH), 256 threads. CTA: 128 query rows of one (b,h).
__global__ void __launch_bounds__(256, 1) attn_mma_kernel() {
    extern __shared__ char dsm[];
    char* sbase = (char*)((((uintptr_t)dsm) + 1023) & ~(uintptr_t)1023);
    uint32_t sb = smem_to_u32(sbase);

    const int tid = threadIdx.x;
    const int lid = tid & 31;
    const int wid = tid >> 5;
    const int bh = blockIdx.y;
    const int qt = (int)gridDim.x - 1 - (int)blockIdx.x;   // heavy tiles first
    const int q0 = qt * 128;

    const size_t hoff = (size_t)bh * (NL*NHD);
    const __nv_bfloat16* qh = g_qh + hoff;
    const __nv_bfloat16* ql = g_ql + hoff;
    const __nv_bfloat16* kh = g_kh + hoff;
    const __nv_bfloat16* kl = g_kl + hoff;
    const __nv_bfloat16* vh = g_vh + hoff;
    const __nv_bfloat16* vl = g_vl + hoff;

    // ---- load Q tile into stage-0 K buffers, pull fragments ----
    cp_tile(sb + 0,     qh + (size_t)q0 * NHD, NHD, tid);
    cp_tile(sb + 16384, ql + (size_t)q0 * NHD, NHD, tid);
    CP_COMMIT();
    CP_WAIT(0);
    __syncthreads();
    const int a_row = wid*16 + (lid & 7) + ((lid >> 3) & 1) * 8;
    const int a_cb  = (lid >> 4) * 8;
    uint32_t Qh[4][4], Ql[4][4];
    #pragma unroll
    for (int kb = 0; kb < 4; kb++) {
        uint32_t sw = SWZ((uint32_t)(a_row * 128 + (kb*16 + a_cb) * 2));
        ldsm4(Qh[kb], sb + 0 + sw);
        ldsm4(Ql[kb], sb + 16384 + sw);
    }
    __syncthreads();   // Q frags in regs; stage-0 buffers free for K/V

    const int g  = lid >> 2;
    const int t4 = lid & 3;
    float m0 = -1e30f, m1 = -1e30f, l0 = 0.f, l1 = 0.f;
    float O[8][4] = {};

    const int b_row = (lid & 7) + ((lid >> 4) & 1) * 8;
    const int b_cb  = ((lid >> 3) & 1) * 8;
    const int v_row = (lid & 7) + ((lid >> 3) & 1) * 8;
    const int v_col = ((lid >> 4) & 1) * 8;
    const int qrow0 = q0 + wid*16 + g;

    attn_issue(sb, 0, 0, kh, kl, vh, vl, tid);
    for (int kt = 0; kt <= qt; kt++) {
        if (kt + 1 <= qt) {
            attn_issue(sb, kt + 1, (kt + 1) & 1, kh, kl, vh, vl, tid);
            CP_WAIT(1);
        } else {
            CP_WAIT(0);
        }
        __syncthreads();
        uint32_t st = sb + (uint32_t)(kt & 1) * 65536;

        // ---- S = Q K^T (3-term compensated) ----
        float sacc[16][4] = {};
        #pragma unroll
        for (int kb = 0; kb < 4; kb++) {
            #pragma unroll
            for (int jj = 0; jj < 8; jj++) {
                uint32_t khf[4], klf[4];
                uint32_t sw = SWZ((uint32_t)((jj*16 + b_row) * 128 + (kb*16 + b_cb) * 2));
                ldsm4(khf, st + 0 + sw);
                ldsm4(klf, st + 16384 + sw);
                mma16816(sacc[2*jj],   Qh[kb], khf[0], khf[1]);
                mma16816(sacc[2*jj+1], Qh[kb], khf[2], khf[3]);
                mma16816(sacc[2*jj],   Ql[kb], khf[0], khf[1]);
                mma16816(sacc[2*jj+1], Ql[kb], khf[2], khf[3]);
                mma16816(sacc[2*jj],   Qh[kb], klf[0], klf[1]);
                mma16816(sacc[2*jj+1], Qh[kb], klf[2], klf[3]);
            }
        }

        // ---- scale (+causal mask on the diagonal tile) ----
        const float scale = 0.125f;
        if (kt == qt) {
            #pragma unroll
            for (int j = 0; j < 16; j++) {
                int col = kt*128 + j*8 + 2*t4;
                #pragma unroll
                for (int e = 0; e < 4; e++) {
                    int c = col + (e & 1);
                    int r = qrow0 + (e >> 1) * 8;
                    sacc[j][e] = (c > r) ? -1e30f : sacc[j][e] * scale;
                }
            }
        } else {
            #pragma unroll
            for (int j = 0; j < 16; j++)
                #pragma unroll
                for (int e = 0; e < 4; e++) sacc[j][e] *= scale;
        }

        // ---- online softmax ----
        float mx0 = -1e30f, mx1 = -1e30f;
        #pragma unroll
        for (int j = 0; j < 16; j++) {
            mx0 = fmaxf(mx0, fmaxf(sacc[j][0], sacc[j][1]));
            mx1 = fmaxf(mx1, fmaxf(sacc[j][2], sacc[j][3]));
        }
        mx0 = fmaxf(mx0, __shfl_xor_sync(0xffffffffu, mx0, 1));
        mx0 = fmaxf(mx0, __shfl_xor_sync(0xffffffffu, mx0, 2));
        mx1 = fmaxf(mx1, __shfl_xor_sync(0xffffffffu, mx1, 1));
        mx1 = fmaxf(mx1, __shfl_xor_sync(0xffffffffu, mx1, 2));

        float mn0 = fmaxf(m0, mx0), mn1 = fmaxf(m1, mx1);
        float al0 = __expf(m0 - mn0), al1 = __expf(m1 - mn1);
        m0 = mn0; m1 = mn1;

        float rs0 = 0.f, rs1 = 0.f;
        #pragma unroll
        for (int j = 0; j < 16; j++) {
            sacc[j][0] = __expf(sacc[j][0] - mn0);
            sacc[j][1] = __expf(sacc[j][1] - mn0);
            sacc[j][2] = __expf(sacc[j][2] - mn1);
            sacc[j][3] = __expf(sacc[j][3] - mn1);
            rs0 += sacc[j][0] + sacc[j][1];
            rs1 += sacc[j][2] + sacc[j][3];
        }
        rs0 += __shfl_xor_sync(0xffffffffu, rs0, 1);
        rs0 += __shfl_xor_sync(0xffffffffu, rs0, 2);
        rs1 += __shfl_xor_sync(0xffffffffu, rs1, 1);
        rs1 += __shfl_xor_sync(0xffffffffu, rs1, 2);
        l0 = l0 * al0 + rs0;
        l1 = l1 * al1 + rs1;
        #pragma unroll
        for (int j = 0; j < 8; j++) {
            O[j][0] *= al0; O[j][1] *= al0;
            O[j][2] *= al1; O[j][3] *= al1;
        }

        // ---- O += P V (3-term compensated) ----
        #pragma unroll
        for (int kb2 = 0; kb2 < 8; kb2++) {
            uint32_t ph[4], pl[4];
            split2(sacc[2*kb2][0],   sacc[2*kb2][1],   ph[0], pl[0]);
            split2(sacc[2*kb2][2],   sacc[2*kb2][3],   ph[1], pl[1]);
            split2(sacc[2*kb2+1][0], sacc[2*kb2+1][1], ph[2], pl[2]);
            split2(sacc[2*kb2+1][2], sacc[2*kb2+1][3], ph[3], pl[3]);
            #pragma unroll
            for (int nn = 0; nn < 4; nn++) {
                uint32_t vhf[4], vlf[4];
                uint32_t sw = SWZ((uint32_t)((kb2*16 + v_row) * 128 + (nn*16 + v_col) * 2));
                ldsm4t(vhf, st + 32768 + sw);
                ldsm4t(vlf, st + 49152 + sw);
                mma16816(O[2*nn],   ph, vhf[0], vhf[1]);
                mma16816(O[2*nn+1], ph, vhf[2], vhf[3]);
                mma16816(O[2*nn],   pl, vhf[0], vhf[1]);
                mma16816(O[2*nn+1], pl, vhf[2], vhf[3]);
                mma16816(O[2*nn],   ph, vlf[0], vlf[1]);
                mma16816(O[2*nn+1], ph, vlf[2], vlf[3]);
            }
        }
        __syncthreads();
    }

    // ---- epilogue: normalize, split hi/lo, write bf16 [t][h*64+hd] ----
    float r0 = 1.0f / l0, r1 = 1.0f / l1;
    const int bb = bh >> 4;
    const int hh = bh & 15;
    const int t0 = bb * NL + qrow0;
    #pragma unroll
    for (int j = 0; j < 8; j++) {
        int hd = hh*64 + j*8 + 2*t4;
        uint32_t hi, lo;
        split2(O[j][0]*r0, O[j][1]*r0, hi, lo);
        *(uint32_t*)&g_ah[(size_t)t0 * ND + hd] = hi;
        *(uint32_t*)&g_al[(size_t)t0 * ND + hd] = lo;
        split2(O[j][2]*r1, O[j][3]*r1, hi, lo);
        *(uint32_t*)&g_ah[(size_t)(t0 + 8) * ND + hd] = hi;
        *(uint32_t*)&g_al[(size_t)(t0 + 8) * ND + hd] = lo;
    }
}

// ---------------- launch -----------------------------------------------------
extern "C" void kernel_launch(void* const* d_in, const int* in_sizes, int n_in,
                              void* d_out, int out_size) {
    const float* X  = (const float*)d_in[0];
    const float* Wq = (const float*)d_in[1];
    const float* bq = (const float*)d_in[2];
    const float* Wk = (const float*)d_in[3];
    const float* bk = (const float*)d_in[4];
    const float* Wv = (const float*)d_in[5];
    const float* bv = (const float*)d_in[6];
    const float* Wo = (const float*)d_in[7];
    const float* bo = (const float*)d_in[8];
    float* out = (float*)d_out;

    rope_tables_kernel<<<(NL*(NHD/2) + 255)/256, 256>>>();

    // resolve device-global addresses (host side, graph-capturable)
    __nv_bfloat16 *xh, *xl, *wh, *wl;
    cudaGetSymbolAddress((void**)&xh, g_xh);
    cudaGetSymbolAddress((void**)&xl, g_xl);
    cudaGetSymbolAddress((void**)&wh, g_wh);
    cudaGetSymbolAddress((void**)&wl, g_wl);

    cvt_kernel<<<(NT*ND/4 + 255)/256, 256>>>(X,  xh, xl, NT*ND/4);
    cvt_kernel<<<(ND*ND/4 + 255)/256, 256>>>(Wq, wh + (size_t)0*ND*ND, wl + (size_t)0*ND*ND, ND*ND/4);
    cvt_kernel<<<(ND*ND/4 + 255)/256, 256>>>(Wk, wh + (size_t)1*ND*ND, wl + (size_t)1*ND*ND, ND*ND/4);
    cvt_kernel<<<(ND*ND/4 + 255)/256, 256>>>(Wv, wh + (size_t)2*ND*ND, wl + (size_t)2*ND*ND, ND*ND/4);
    cvt_kernel<<<(ND*ND/4 + 255)/256, 256>>>(Wo, wh + (size_t)3*ND*ND, wl + (size_t)3*ND*ND, ND*ND/4);

    cudaFuncSetAttribute(qkv_mma_kernel2, cudaFuncAttributeMaxDynamicSharedMemorySize, GEMM_SMEM_BYTES);
    cudaFuncSetAttribute(out_mma_kernel,  cudaFuncAttributeMaxDynamicSharedMemorySize, GEMM_SMEM_BYTES);
    cudaFuncSetAttribute(attn_mma_kernel, cudaFuncAttributeMaxDynamicSharedMemorySize, ATT_SMEM_BYTES);

    qkv_mma_kernel2<<<dim3(ND/128, NT/128, 3), 256, GEMM_SMEM_BYTES>>>(bq, bk, bv);

    attn_mma_kernel<<<dim3(NL/128, NB*NH), 256, ATT_SMEM_BYTES>>>();

    out_mma_kernel<<<dim3(ND/128, NT/128), 256, GEMM_SMEM_BYTES>>>(bo, out);
}

// round 11
// speedup vs baseline: 3.3384x; 1.0403x over previous
#include <cuda_runtime.h>
#include <cuda_bf16.h>
#include <stdint.h>
#include <math.h>

#define NB 4
#define NL 2048
#define ND 1024
#define NH 16
#define NHD 64
#define NT (NB*NL)

// ---------------- scratch (device globals: no allocations allowed) ----------
__device__ __nv_bfloat16 g_xh[(size_t)NT*ND];
__device__ __nv_bfloat16 g_xl[(size_t)NT*ND];
__device__ __nv_bfloat16 g_wh[(size_t)4*ND*ND];   // Wq,Wk,Wv,Wo
__device__ __nv_bfloat16 g_wl[(size_t)4*ND*ND];
__device__ __nv_bfloat16 g_qh[(size_t)NB*NH*NL*NHD];  // [bh][l][hd]
__device__ __nv_bfloat16 g_ql[(size_t)NB*NH*NL*NHD];
__device__ __nv_bfloat16 g_kh[(size_t)NB*NH*NL*NHD];
__device__ __nv_bfloat16 g_kl[(size_t)NB*NH*NL*NHD];
__device__ __nv_bfloat16 g_vh[(size_t)NB*NH*NL*NHD];
__device__ __nv_bfloat16 g_vl[(size_t)NB*NH*NL*NHD];
__device__ __nv_bfloat16 g_ah[(size_t)NT*ND];     // attention out [t][h*64+hd]
__device__ __nv_bfloat16 g_al[(size_t)NT*ND];
__device__ float g_cos[NL*(NHD/2)];
__device__ float g_sin[NL*(NHD/2)];

// ---------------- helpers ----------------------------------------------------
__device__ __forceinline__ uint32_t smem_to_u32(const void* smem_ptr) {
    uint32_t addr;
    asm("{ .reg .u64 tmp; cvta.to.shared.u64 tmp, %1; cvt.u32.u64 %0, tmp; }"
        : "=r"(addr) : "l"(smem_ptr));
    return addr;
}
#define SWZ(off)   ((off) ^ (((off) >> 3) & 0x70))   // 128B rows
#define SWZ64(off) ((off) ^ (((off) >> 3) & 0x30))   // 64B rows

__device__ __forceinline__ void ldsm4(uint32_t* r, uint32_t a) {
    asm volatile("ldmatrix.sync.aligned.m8n8.x4.shared.b16 {%0,%1,%2,%3}, [%4];"
        : "=r"(r[0]), "=r"(r[1]), "=r"(r[2]), "=r"(r[3]) : "r"(a));
}
__device__ __forceinline__ void ldsm4t(uint32_t* r, uint32_t a) {
    asm volatile("ldmatrix.sync.aligned.m8n8.x4.trans.shared.b16 {%0,%1,%2,%3}, [%4];"
        : "=r"(r[0]), "=r"(r[1]), "=r"(r[2]), "=r"(r[3]) : "r"(a));
}
__device__ __forceinline__ void mma16816(float* c, const uint32_t* a,
                                         uint32_t b0, uint32_t b1) {
    asm volatile(
        "mma.sync.aligned.m16n8k16.row.col.f32.bf16.bf16.f32 "
        "{%0,%1,%2,%3}, {%4,%5,%6,%7}, {%8,%9}, {%0,%1,%2,%3};"
        : "+f"(c[0]), "+f"(c[1]), "+f"(c[2]), "+f"(c[3])
        : "r"(a[0]), "r"(a[1]), "r"(a[2]), "r"(a[3]), "r"(b0), "r"(b1));
}
__device__ __forceinline__ void split2(float a, float b, uint32_t& hi, uint32_t& lo) {
    __nv_bfloat162 h, l;
    h.x = __float2bfloat16(a); h.y = __float2bfloat16(b);
    l.x = __float2bfloat16(a - __bfloat162float(h.x));
    l.y = __float2bfloat16(b - __bfloat162float(h.y));
    hi = *(uint32_t*)&h; lo = *(uint32_t*)&l;
}
__device__ __forceinline__ void cp_async16(uint32_t sdst, const void* gsrc) {
    asm volatile("cp.async.cg.shared.global [%0], [%1], 16;"
        :: "r"(sdst), "l"(gsrc));
}
#define CP_COMMIT() asm volatile("cp.async.commit_group;" ::: "memory")
#define CP_WAIT(n)  asm volatile("cp.async.wait_group %0;" :: "n"(n) : "memory")

// [128 x 64] bf16 tile (row stride gstride elems) -> 128B-row swizzled smem
__device__ __forceinline__ void cp_tile(uint32_t sdst, const __nv_bfloat16* gsrc,
                                        int gstride, int tid) {
    #pragma unroll
    for (int it = 0; it < 4; it++) {
        int idx = tid + it * 256;          // 0..1023
        int row = idx >> 3, seg = idx & 7;
        cp_async16(sdst + SWZ((uint32_t)(row * 128 + seg * 16)),
                   gsrc + (size_t)row * gstride + seg * 8);
    }
}
// [128 x 32] bf16 tile -> 64B-row SW64 smem
__device__ __forceinline__ void cp_tile32(uint32_t sdst, const __nv_bfloat16* gsrc,
                                          int gstride, int tid) {
    #pragma unroll
    for (int it = 0; it < 2; it++) {
        int idx = tid + it * 256;          // 0..511
        int row = idx >> 2, seg = idx & 3;
        cp_async16(sdst + SWZ64((uint32_t)(row * 64 + seg * 16)),
                   gsrc + (size_t)row * gstride + seg * 8);
    }
}

// ---------------- K0a: RoPE tables (fp64 for accuracy) -----------------------
__global__ void rope_tables_kernel() {
    int idx = blockIdx.x * 256 + threadIdx.x;
    if (idx >= NL * (NHD/2)) return;
    int l = idx >> 5;
    int i = idx & 31;
    double inv = exp(-((double)(2*i) / (double)NHD) * log(10000.0));
    double a = (double)l * inv;
    g_cos[idx] = (float)cos(a);
    g_sin[idx] = (float)sin(a);
}

// ---------------- K0b: fp32 -> hi/lo bf16 converters -------------------------
__global__ void cvt_kernel(const float* __restrict__ src,
                           __nv_bfloat16* __restrict__ dh,
                           __nv_bfloat16* __restrict__ dl, int n4) {
    int i = blockIdx.x * 256 + threadIdx.x;
    if (i >= n4) return;
    float4 x = ((const float4*)src)[i];
    uint32_t h01, h23, l01, l23;
    split2(x.x, x.y, h01, l01);
    split2(x.z, x.w, h23, l23);
    ((uint2*)dh)[i] = make_uint2(h01, h23);
    ((uint2*)dl)[i] = make_uint2(l01, l23);
}
struct WPtrs { const float* p[4]; };
__global__ void cvt_w_kernel(WPtrs wp) {
    const int z = blockIdx.y;
    const float* src = wp.p[z];
    int i = blockIdx.x * 256 + threadIdx.x;
    if (i >= ND*ND/4) return;
    float4 x = ((const float4*)src)[i];
    uint32_t h01, h23, l01, l23;
    split2(x.x, x.y, h01, l01);
    split2(x.z, x.w, h23, l23);
    size_t base = (size_t)z * (ND*ND/4);
    ((uint2*)g_wh)[base + i] = make_uint2(h01, h23);
    ((uint2*)g_wl)[base + i] = make_uint2(l01, l23);
}

// ---------------- GEMM mainloop: K-chunk 32, 2-stage, 1 barrier/stage --------
// stage block 32KB: {AH:0, AL:8K, BH:16K, BL:24K}; stages at 0 / 32768
#define GEMM_SMEM_BYTES (2*32768 + 1024)
#define NSTAGES_G (ND/32)      // 32

__device__ __forceinline__ void gemm_issue(
    uint32_t sb, int s, const __nv_bfloat16* Ah, const __nv_bfloat16* Al,
    const __nv_bfloat16* Bh, const __nv_bfloat16* Bl, int tid)
{
    uint32_t st = sb + (uint32_t)(s & 1) * 32768;
    int k0 = s * 32;
    cp_tile32(st + 0,     Ah + k0, ND, tid);
    cp_tile32(st + 8192,  Al + k0, ND, tid);
    cp_tile32(st + 16384, Bh + k0, ND, tid);
    cp_tile32(st + 24576, Bl + k0, ND, tid);
    CP_COMMIT();
}

__device__ __forceinline__ void gemm_mainloop_bf16(
    const __nv_bfloat16* __restrict__ Ah, const __nv_bfloat16* __restrict__ Al,
    const __nv_bfloat16* __restrict__ Bh, const __nv_bfloat16* __restrict__ Bl,
    uint32_t sb, float acc[2][8][4])
{
    const int tid = threadIdx.x;
    const int lid = tid & 31;
    const int wid = tid >> 5;
    const int wm = wid >> 1;
    const int wn = wid & 1;

    const int a_row = wm*32 + (lid & 7) + ((lid >> 3) & 1) * 8;
    const int a_cb  = (lid >> 4) * 8;
    const int b_row = wn*64 + (lid & 7) + ((lid >> 4) & 1) * 8;
    const int b_cb  = ((lid >> 3) & 1) * 8;

    gemm_issue(sb, 0, Ah, Al, Bh, Bl, tid);
    for (int s = 0; s < NSTAGES_G; s++) {
        CP_WAIT(0);
        __syncthreads();     // all reads of buffer (s-1)&1 retired; safe to refill
        if (s + 1 < NSTAGES_G)
            gemm_issue(sb, s + 1, Ah, Al, Bh, Bl, tid);
        uint32_t st = sb + (uint32_t)(s & 1) * 32768;

        #pragma unroll
        for (int ks = 0; ks < 2; ks++) {
            const int k0 = ks * 16;
            uint32_t ah[2][4], al[2][4], bh[4][4], bl[4][4];
            #pragma unroll
            for (int i = 0; i < 2; i++) {
                uint32_t sw = SWZ64((uint32_t)((a_row + i*16) * 64 + (k0 + a_cb) * 2));
                ldsm4(ah[i], st + 0 + sw);
                ldsm4(al[i], st + 8192 + sw);
            }
            #pragma unroll
            for (int jj = 0; jj < 4; jj++) {
                uint32_t sw = SWZ64((uint32_t)((b_row + jj*16) * 64 + (k0 + b_cb) * 2));
                ldsm4(bh[jj], st + 16384 + sw);
                ldsm4(bl[jj], st + 24576 + sw);
            }
            #pragma unroll
            for (int i = 0; i < 2; i++)
                #pragma unroll
                for (int jj = 0; jj < 4; jj++) {
                    mma16816(acc[i][2*jj],   ah[i], bh[jj][0], bh[jj][1]);
                    mma16816(acc[i][2*jj+1], ah[i], bh[jj][2], bh[jj][3]);
                    mma16816(acc[i][2*jj],   ah[i], bl[jj][0], bl[jj][1]);
                    mma16816(acc[i][2*jj+1], ah[i], bl[jj][2], bl[jj][3]);
                    mma16816(acc[i][2*jj],   al[i], bh[jj][0], bh[jj][1]);
                    mma16816(acc[i][2*jj+1], al[i], bh[jj][2], bh[jj][3]);
                }
        }
    }
}

// ---------------- K1: fused QKV projection + RoPE ----------------------------
__global__ void __launch_bounds__(256, 2)
qkv_mma_kernel(const float* __restrict__ bq, const float* __restrict__ bk,
               const float* __restrict__ bv)
{
    extern __shared__ char dsm[];
    char* sbase = (char*)((((uintptr_t)dsm) + 1023) & ~(uintptr_t)1023);
    uint32_t sb = smem_to_u32(sbase);
    const int tid = threadIdx.x;
    const int lid = tid & 31;
    const int wid = tid >> 5;
    const int wm = wid >> 1;
    const int wn = wid & 1;

    const int z = blockIdx.z;
    const float* bias = (z == 0) ? bq : (z == 1) ? bk : bv;
    __nv_bfloat16* dsth = (z == 0) ? g_qh : (z == 1) ? g_kh : g_vh;
    __nv_bfloat16* dstl = (z == 0) ? g_ql : (z == 1) ? g_kl : g_vl;

    const int mBase = blockIdx.y * 128;
    const int nBase = blockIdx.x * 128;

    float acc[2][8][4] = {};
    gemm_mainloop_bf16(g_xh + (size_t)mBase * ND, g_xl + (size_t)mBase * ND,
                       g_wh + (size_t)z * ND * ND + (size_t)nBase * ND,
                       g_wl + (size_t)z * ND * ND + (size_t)nBase * ND,
                       sb, acc);

    const int g  = lid >> 2;
    const int t4 = lid & 3;
    #pragma unroll
    for (int i = 0; i < 2; i++) {
        #pragma unroll
        for (int rr = 0; rr < 2; rr++) {
            int t = mBase + wm*32 + i*16 + g + rr*8;
            int b = t >> 11;
            int l = t & (NL - 1);
            #pragma unroll
            for (int j = 0; j < 8; j++) {
                int c = nBase + wn*64 + j*8 + 2*t4;
                float y0 = acc[i][j][rr*2+0] + bias[c];
                float y1 = acc[i][j][rr*2+1] + bias[c+1];
                if (z < 2) {
                    int p0 = (c & 63) >> 1;
                    float co = g_cos[l*32 + p0], si = g_sin[l*32 + p0];
                    float e = y0, o = y1;
                    y0 = e*co - o*si;
                    y1 = e*si + o*co;
                }
                int h  = c >> 6;
                int hd = c & 63;
                size_t idx = (((size_t)(b*NH + h))*NL + l)*NHD + hd;
                uint32_t hi, lo;
                split2(y0, y1, hi, lo);
                *(uint32_t*)&dsth[idx] = hi;
                *(uint32_t*)&dstl[idx] = lo;
            }
        }
    }
}

// ---------------- K3: output projection --------------------------------------
__global__ void __launch_bounds__(256, 2)
out_mma_kernel(const float* __restrict__ bias, float* __restrict__ out)
{
    extern __shared__ char dsm[];
    char* sbase = (char*)((((uintptr_t)dsm) + 1023) & ~(uintptr_t)1023);
    uint32_t sb = smem_to_u32(sbase);
    const int tid = threadIdx.x;
    const int lid = tid & 31;
    const int wid = tid >> 5;
    const int wm = wid >> 1;
    const int wn = wid & 1;

    const int mBase = blockIdx.y * 128;
    const int nBase = blockIdx.x * 128;

    float acc[2][8][4] = {};
    gemm_mainloop_bf16(g_ah + (size_t)mBase * ND, g_al + (size_t)mBase * ND,
                       g_wh + (size_t)3 * ND * ND + (size_t)nBase * ND,
                       g_wl + (size_t)3 * ND * ND + (size_t)nBase * ND,
                       sb, acc);

    const int g  = lid >> 2;
    const int t4 = lid & 3;
    #pragma unroll
    for (int i = 0; i < 2; i++) {
        #pragma unroll
        for (int rr = 0; rr < 2; rr++) {
            int t = mBase + wm*32 + i*16 + g + rr*8;
            #pragma unroll
            for (int j = 0; j < 8; j++) {
                int c = nBase + wn*64 + j*8 + 2*t4;
                *(float2*)&out[(size_t)t * ND + c] = make_float2(
                    acc[i][j][rr*2+0] + bias[c],
                    acc[i][j][rr*2+1] + bias[c+1]);
            }
        }
    }
}

// ======================= K2: flash attention (bf16 + cp.async) ===============
// stage block 64KB: {KH:0, KL:16K, VH:32K, VL:48K}; stages at 0 / 65536
#define ATT_SMEM_BYTES (2*65536 + 1024)

__device__ __forceinline__ void attn_issue(uint32_t sb, int kt,
                                           const __nv_bfloat16* kh, const __nv_bfloat16* kl,
                                           const __nv_bfloat16* vh, const __nv_bfloat16* vl,
                                           int tid) {
    uint32_t st = sb + (uint32_t)(kt & 1) * 65536;
    size_t off = (size_t)kt * 128 * NHD;
    cp_tile(st + 0,     kh + off, NHD, tid);
    cp_tile(st + 16384, kl + off, NHD, tid);
    cp_tile(st + 32768, vh + off, NHD, tid);
    cp_tile(st + 49152, vl + off, NHD, tid);
    CP_COMMIT();
}

// grid (NL/128, NB*NH), 256 threads. CTA: 128 query rows of one (b,h).
__global__ void __launch_bounds__(256, 1) attn_mma_kernel() {
    extern __shared__ char dsm[];
    char* sbase = (char*)((((uintptr_t)dsm) + 1023) & ~(uintptr_t)1023);
    uint32_t sb = smem_to_u32(sbase);

    const int tid = threadIdx.x;
    const int lid = tid & 31;
    const int wid = tid >> 5;
    const int bh = blockIdx.y;
    const int qt = (int)gridDim.x - 1 - (int)blockIdx.x;   // heavy tiles first
    const int q0 = qt * 128;

    const size_t hoff = (size_t)bh * (NL*NHD);
    const __nv_bfloat16* qh = g_qh + hoff;
    const __nv_bfloat16* ql = g_ql + hoff;
    const __nv_bfloat16* kh = g_kh + hoff;
    const __nv_bfloat16* kl = g_kl + hoff;
    const __nv_bfloat16* vh = g_vh + hoff;
    const __nv_bfloat16* vl = g_vl + hoff;

    // ---- load Q tile into stage-0 K buffers, pull fragments ----
    cp_tile(sb + 0,     qh + (size_t)q0 * NHD, NHD, tid);
    cp_tile(sb + 16384, ql + (size_t)q0 * NHD, NHD, tid);
    CP_COMMIT();
    CP_WAIT(0);
    __syncthreads();
    const int a_row = wid*16 + (lid & 7) + ((lid >> 3) & 1) * 8;
    const int a_cb  = (lid >> 4) * 8;
    uint32_t Qh[4][4], Ql[4][4];
    #pragma unroll
    for (int kb = 0; kb < 4; kb++) {
        uint32_t sw = SWZ((uint32_t)(a_row * 128 + (kb*16 + a_cb) * 2));
        ldsm4(Qh[kb], sb + 0 + sw);
        ldsm4(Ql[kb], sb + 16384 + sw);
    }
    __syncthreads();   // Q frags in regs; stage-0 buffers free for K/V

    const int g  = lid >> 2;
    const int t4 = lid & 3;
    float m0 = -1e30f, m1 = -1e30f, l0 = 0.f, l1 = 0.f;
    float O[8][4] = {};

    const int b_row = (lid & 7) + ((lid >> 4) & 1) * 8;
    const int b_cb  = ((lid >> 3) & 1) * 8;
    const int v_row = (lid & 7) + ((lid >> 3) & 1) * 8;
    const int v_col = ((lid >> 4) & 1) * 8;
    const int qrow0 = q0 + wid*16 + g;

    attn_issue(sb, 0, kh, kl, vh, vl, tid);
    for (int kt = 0; kt <= qt; kt++) {
        CP_WAIT(0);
        __syncthreads();    // reads of buffer (kt-1)&1 retired; safe to refill
        if (kt + 1 <= qt)
            attn_issue(sb, kt + 1, kh, kl, vh, vl, tid);
        uint32_t st = sb + (uint32_t)(kt & 1) * 65536;

        // ---- S = Q K^T (3-term compensated) ----
        float sacc[16][4] = {};
        #pragma unroll
        for (int kb = 0; kb < 4; kb++) {
            #pragma unroll
            for (int jj = 0; jj < 8; jj++) {
                uint32_t khf[4], klf[4];
                uint32_t sw = SWZ((uint32_t)((jj*16 + b_row) * 128 + (kb*16 + b_cb) * 2));
                ldsm4(khf, st + 0 + sw);
                ldsm4(klf, st + 16384 + sw);
                mma16816(sacc[2*jj],   Qh[kb], khf[0], khf[1]);
                mma16816(sacc[2*jj+1], Qh[kb], khf[2], khf[3]);
                mma16816(sacc[2*jj],   Ql[kb], khf[0], khf[1]);
                mma16816(sacc[2*jj+1], Ql[kb], khf[2], khf[3]);
                mma16816(sacc[2*jj],   Qh[kb], klf[0], klf[1]);
                mma16816(sacc[2*jj+1], Qh[kb], klf[2], klf[3]);
            }
        }

        // ---- scale (+causal mask on the diagonal tile) ----
        const float scale = 0.125f;
        if (kt == qt) {
            #pragma unroll
            for (int j = 0; j < 16; j++) {
                int col = kt*128 + j*8 + 2*t4;
                #pragma unroll
                for (int e = 0; e < 4; e++) {
                    int c = col + (e & 1);
                    int r = qrow0 + (e >> 1) * 8;
                    sacc[j][e] = (c > r) ? -1e30f : sacc[j][e] * scale;
                }
            }
        } else {
            #pragma unroll
            for (int j = 0; j < 16; j++)
                #pragma unroll
                for (int e = 0; e < 4; e++) sacc[j][e] *= scale;
        }

        // ---- online softmax ----
        float mx0 = -1e30f, mx1 = -1e30f;
        #pragma unroll
        for (int j = 0; j < 16; j++) {
            mx0 = fmaxf(mx0, fmaxf(sacc[j][0], sacc[j][1]));
            mx1 = fmaxf(mx1, fmaxf(sacc[j][2], sacc[j][3]));
        }
        mx0 = fmaxf(mx0, __shfl_xor_sync(0xffffffffu, mx0, 1));
        mx0 = fmaxf(mx0, __shfl_xor_sync(0xffffffffu, mx0, 2));
        mx1 = fmaxf(mx1, __shfl_xor_sync(0xffffffffu, mx1, 1));
        mx1 = fmaxf(mx1, __shfl_xor_sync(0xffffffffu, mx1, 2));

        float mn0 = fmaxf(m0, mx0), mn1 = fmaxf(m1, mx1);
        float al0 = __expf(m0 - mn0), al1 = __expf(m1 - mn1);
        m0 = mn0; m1 = mn1;

        float rs0 = 0.f, rs1 = 0.f;
        #pragma unroll
        for (int j = 0; j < 16; j++) {
            sacc[j][0] = __expf(sacc[j][0] - mn0);
            sacc[j][1] = __expf(sacc[j][1] - mn0);
            sacc[j][2] = __expf(sacc[j][2] - mn1);
            sacc[j][3] = __expf(sacc[j][3] - mn1);
            rs0 += sacc[j][0] + sacc[j][1];
            rs1 += sacc[j][2] + sacc[j][3];
        }
        rs0 += __shfl_xor_sync(0xffffffffu, rs0, 1);
        rs0 += __shfl_xor_sync(0xffffffffu, rs0, 2);
        rs1 += __shfl_xor_sync(0xffffffffu, rs1, 1);
        rs1 += __shfl_xor_sync(0xffffffffu, rs1, 2);
        l0 = l0 * al0 + rs0;
        l1 = l1 * al1 + rs1;
        #pragma unroll
        for (int j = 0; j < 8; j++) {
            O[j][0] *= al0; O[j][1] *= al0;
            O[j][2] *= al1; O[j][3] *= al1;
        }

        // ---- O += P V (3-term compensated) ----
        #pragma unroll
        for (int kb2 = 0; kb2 < 8; kb2++) {
            uint32_t ph[4], pl[4];
            split2(sacc[2*kb2][0],   sacc[2*kb2][1],   ph[0], pl[0]);
            split2(sacc[2*kb2][2],   sacc[2*kb2][3],   ph[1], pl[1]);
            split2(sacc[2*kb2+1][0], sacc[2*kb2+1][1], ph[2], pl[2]);
            split2(sacc[2*kb2+1][2], sacc[2*kb2+1][3], ph[3], pl[3]);
            #pragma unroll
            for (int nn = 0; nn < 4; nn++) {
                uint32_t vhf[4], vlf[4];
                uint32_t sw = SWZ((uint32_t)((kb2*16 + v_row) * 128 + (nn*16 + v_col) * 2));
                ldsm4t(vhf, st + 32768 + sw);
                ldsm4t(vlf, st + 49152 + sw);
                mma16816(O[2*nn],   ph, vhf[0], vhf[1]);
                mma16816(O[2*nn+1], ph, vhf[2], vhf[3]);
                mma16816(O[2*nn],   pl, vhf[0], vhf[1]);
                mma16816(O[2*nn+1], pl, vhf[2], vhf[3]);
                mma16816(O[2*nn],   ph, vl != 0 ? vlf[0] : vlf[0], vlf[1]);
                mma16816(O[2*nn+1], ph, vlf[2], vlf[3]);
            }
        }
    }

    // ---- epilogue: normalize, split hi/lo, write bf16 [t][h*64+hd] ----
    float r0 = 1.0f / l0, r1 = 1.0f / l1;
    const int bb = bh >> 4;
    const int hh = bh & 15;
    const int t0 = bb * NL + qrow0;
    #pragma unroll
    for (int j = 0; j < 8; j++) {
        int hd = hh*64 + j*8 + 2*t4;
        uint32_t hi, lo;
        split2(O[j][0]*r0, O[j][1]*r0, hi, lo);
        *(uint32_t*)&g_ah[(size_t)t0 * ND + hd] = hi;
        *(uint32_t*)&g_al[(size_t)t0 * ND + hd] = lo;
        split2(O[j][2]*r1, O[j][3]*r1, hi, lo);
        *(uint32_t*)&g_ah[(size_t)(t0 + 8) * ND + hd] = hi;
        *(uint32_t*)&g_al[(size_t)(t0 + 8) * ND + hd] = lo;
    }
}

// ---------------- launch -----------------------------------------------------
extern "C" void kernel_launch(void* const* d_in, const int* in_sizes, int n_in,
                              void* d_out, int out_size) {
    const float* X  = (const float*)d_in[0];
    const float* Wq = (const float*)d_in[1];
    const float* bq = (const float*)d_in[2];
    const float* Wk = (const float*)d_in[3];
    const float* bk = (const float*)d_in[4];
    const float* Wv = (const float*)d_in[5];
    const float* bv = (const float*)d_in[6];
    const float* Wo = (const float*)d_in[7];
    const float* bo = (const float*)d_in[8];
    float* out = (float*)d_out;

    rope_tables_kernel<<<(NL*(NHD/2) + 255)/256, 256>>>();

    __nv_bfloat16 *xh, *xl;
    cudaGetSymbolAddress((void**)&xh, g_xh);
    cudaGetSymbolAddress((void**)&xl, g_xl);

    cvt_kernel<<<(NT*ND/4 + 255)/256, 256>>>(X, xh, xl, NT*ND/4);
    WPtrs wp; wp.p[0] = Wq; wp.p[1] = Wk; wp.p[2] = Wv; wp.p[3] = Wo;
    cvt_w_kernel<<<dim3((ND*ND/4 + 255)/256, 4), 256>>>(wp);

    cudaFuncSetAttribute(qkv_mma_kernel, cudaFuncAttributeMaxDynamicSharedMemorySize, GEMM_SMEM_BYTES);
    cudaFuncSetAttribute(out_mma_kernel, cudaFuncAttributeMaxDynamicSharedMemorySize, GEMM_SMEM_BYTES);
    cudaFuncSetAttribute(attn_mma_kernel, cudaFuncAttributeMaxDynamicSharedMemorySize, ATT_SMEM_BYTES);

    qkv_mma_kernel<<<dim3(ND/128, NT/128, 3), 256, GEMM_SMEM_BYTES>>>(bq, bk, bv);

    attn_mma_kernel<<<dim3(NL/128, NB*NH), 256, ATT_SMEM_BYTES>>>();

    out_mma_kernel<<<dim3(ND/128, NT/128), 256, GEMM_SMEM_BYTES>>>(bo, out);
}